// round 1
// baseline (speedup 1.0000x reference)
#include <cuda_runtime.h>
#include <math.h>

#define Bsz 32
#define Ssz 512
#define Tsz 180
#define Dsz 512
#define Fsz 2048
#define Lsz 6
#define Hsz 8
#define DHsz 64

// ---------------- scratch buffers (device globals; no allocation) ----------------
__device__ float g_h   [Bsz*Ssz*Dsz];   // encoder activations / memory
__device__ float g_tmp [Bsz*Ssz*Dsz];   // attention output (concat heads)
__device__ float g_q   [Bsz*Ssz*Dsz];
__device__ float g_k   [Bsz*Ssz*Dsz];
__device__ float g_v   [Bsz*Ssz*Dsz];
__device__ float g_ffn [Bsz*Ssz*Fsz];   // FFN hidden
__device__ float g_d   [Bsz*Tsz*Dsz];   // decoder activations
__device__ float g_dq  [Bsz*Tsz*Dsz];
__device__ float g_dtmp[Bsz*Tsz*Dsz];

// ---------------- utility ----------------
__device__ __forceinline__ float warpSum(float v) {
    #pragma unroll
    for (int o = 16; o; o >>= 1) v += __shfl_xor_sync(0xffffffffu, v, o);
    return v;
}
__device__ __forceinline__ float warpMax(float v) {
    #pragma unroll
    for (int o = 16; o; o >>= 1) v = fmaxf(v, __shfl_xor_sync(0xffffffffu, v, o));
    return v;
}

// ---------------- SGEMM: C[M,N] = A[M,K] @ B[K,N] + bias[N], optional ReLU ------
// BM=BN=128, BK=8, 256 threads, 8x8 per thread. M,N % 128 == 0, K % 8 == 0.
__global__ __launch_bounds__(256) void sgemm_bias(
    const float* __restrict__ A, const float* __restrict__ B,
    const float* __restrict__ bias, float* __restrict__ C,
    int M, int N, int K, int doRelu)
{
    __shared__ float As[8][128];
    __shared__ float Bs[8][128];

    const int tid = threadIdx.x;
    const int bm = blockIdx.y * 128;
    const int bn = blockIdx.x * 128;

    const int arow = tid >> 1;          // 0..127
    const int acol = (tid & 1) << 2;    // 0 or 4
    const int brow = tid >> 5;          // 0..7
    const int bcol = (tid & 31) << 2;   // 0..124

    const int tx = (tid & 15) << 3;     // col offset 0..120
    const int ty = (tid >> 4) << 3;     // row offset 0..120

    float acc[8][8];
    #pragma unroll
    for (int i = 0; i < 8; i++)
        #pragma unroll
        for (int j = 0; j < 8; j++) acc[i][j] = 0.f;

    const float* Aptr = A + (size_t)bm * K;
    const float* Bptr = B + bn;

    for (int k0 = 0; k0 < K; k0 += 8) {
        float4 a4 = *(const float4*)(Aptr + (size_t)arow * K + k0 + acol);
        As[acol + 0][arow] = a4.x;
        As[acol + 1][arow] = a4.y;
        As[acol + 2][arow] = a4.z;
        As[acol + 3][arow] = a4.w;
        float4 b4 = *(const float4*)(Bptr + (size_t)(k0 + brow) * N + bcol);
        *(float4*)&Bs[brow][bcol] = b4;
        __syncthreads();

        #pragma unroll
        for (int kk = 0; kk < 8; kk++) {
            float ar[8], br[8];
            #pragma unroll
            for (int i = 0; i < 8; i++) ar[i] = As[kk][ty + i];
            #pragma unroll
            for (int j = 0; j < 8; j++) br[j] = Bs[kk][tx + j];
            #pragma unroll
            for (int i = 0; i < 8; i++)
                #pragma unroll
                for (int j = 0; j < 8; j++)
                    acc[i][j] = fmaf(ar[i], br[j], acc[i][j]);
        }
        __syncthreads();
    }

    #pragma unroll
    for (int i = 0; i < 8; i++) {
        float* crow = C + (size_t)(bm + ty + i) * N + bn + tx;
        #pragma unroll
        for (int j = 0; j < 8; j += 4) {
            float4 o;
            o.x = acc[i][j + 0] + bias[bn + tx + j + 0];
            o.y = acc[i][j + 1] + bias[bn + tx + j + 1];
            o.z = acc[i][j + 2] + bias[bn + tx + j + 2];
            o.w = acc[i][j + 3] + bias[bn + tx + j + 3];
            if (doRelu) {
                o.x = fmaxf(o.x, 0.f); o.y = fmaxf(o.y, 0.f);
                o.z = fmaxf(o.z, 0.f); o.w = fmaxf(o.w, 0.f);
            }
            *(float4*)(crow + j) = o;
        }
    }
}

// ---------------- attention: one block per (b, h, query row) --------------------
// Q [B,Sq,D], K/V [B,Sk,D]; head h occupies cols h*64..h*64+63. O [B,Sq,D].
__global__ __launch_bounds__(128) void attn_kernel(
    const float* __restrict__ Q, const float* __restrict__ K,
    const float* __restrict__ V, float* __restrict__ O,
    int Sq, int Sk, int causal)
{
    const int qi = blockIdx.x, h = blockIdx.y, b = blockIdx.z;
    const int tid = threadIdx.x;
    const int lane = tid & 31, warp = tid >> 5;

    __shared__ float qv[64];
    __shared__ float sc[512];
    __shared__ float red[12];
    __shared__ float ored[64];

    const size_t hoff = (size_t)h * DHsz;
    const float* qrow = Q + ((size_t)(b * Sq + qi) * Dsz) + hoff;
    if (tid < 64) qv[tid] = qrow[tid];
    __syncthreads();

    const int nk = causal ? (qi + 1) : Sk;

    // scores: one warp per key, lanes over d (coalesced)
    for (int ki = warp; ki < nk; ki += 4) {
        const float* krow = K + ((size_t)(b * Sk + ki) * Dsz) + hoff;
        float p = qv[lane] * krow[lane] + qv[lane + 32] * krow[lane + 32];
        p = warpSum(p);
        if (lane == 0) sc[ki] = p * 0.125f;   // 1/sqrt(64)
    }
    __syncthreads();

    // softmax
    float m = -1e30f;
    for (int i = tid; i < nk; i += 128) m = fmaxf(m, sc[i]);
    m = warpMax(m);
    if (lane == 0) red[warp] = m;
    __syncthreads();
    m = fmaxf(fmaxf(red[0], red[1]), fmaxf(red[2], red[3]));

    float s = 0.f;
    for (int i = tid; i < nk; i += 128) {
        float e = expf(sc[i] - m);
        sc[i] = e;
        s += e;
    }
    s = warpSum(s);
    if (lane == 0) red[4 + warp] = s;
    __syncthreads();
    const float inv = 1.f / (red[4] + red[5] + red[6] + red[7]);

    // output: 2 key-partitions x 64 dims
    const int d = tid & 63;
    const int part = tid >> 6;
    float acc = 0.f;
    for (int ki = part; ki < nk; ki += 2)
        acc += sc[ki] * V[((size_t)(b * Sk + ki) * Dsz) + hoff + d];
    if (part == 0) ored[d] = acc;
    __syncthreads();
    if (part == 1)
        O[((size_t)(b * Sq + qi) * Dsz) + hoff + d] = (ored[d] + acc) * inv;
}

// ---------------- residual + LayerNorm: h = LN(h + r) ---------------------------
__global__ __launch_bounds__(128) void add_ln_kernel(
    float* __restrict__ h, const float* __restrict__ r,
    const float* __restrict__ scale, const float* __restrict__ bias)
{
    const int row = blockIdx.x;
    const int tid = threadIdx.x;
    const int lane = tid & 31, warp = tid >> 5;
    float* hp = h + (size_t)row * Dsz;
    const float* rp = r + (size_t)row * Dsz;

    float4 hv = *(const float4*)(hp + tid * 4);
    float4 rv = *(const float4*)(rp + tid * 4);
    float v0 = hv.x + rv.x, v1 = hv.y + rv.y, v2 = hv.z + rv.z, v3 = hv.w + rv.w;

    float sum = v0 + v1 + v2 + v3;
    float sq  = v0*v0 + v1*v1 + v2*v2 + v3*v3;
    sum = warpSum(sum); sq = warpSum(sq);

    __shared__ float s1[4], s2[4];
    if (lane == 0) { s1[warp] = sum; s2[warp] = sq; }
    __syncthreads();
    sum = s1[0] + s1[1] + s1[2] + s1[3];
    sq  = s2[0] + s2[1] + s2[2] + s2[3];

    const float mu = sum * (1.f / Dsz);
    const float var = sq * (1.f / Dsz) - mu * mu;
    const float rs = rsqrtf(var + 1e-5f);

    float4 sc4 = *(const float4*)(scale + tid * 4);
    float4 bi4 = *(const float4*)(bias + tid * 4);
    float4 o;
    o.x = (v0 - mu) * rs * sc4.x + bi4.x;
    o.y = (v1 - mu) * rs * sc4.y + bi4.y;
    o.z = (v2 - mu) * rs * sc4.z + bi4.z;
    o.w = (v3 - mu) * rs * sc4.w + bi4.w;
    *(float4*)(hp + tid * 4) = o;
}

// ---------------- embeddings with analytic positional encoding ------------------
__device__ __forceinline__ float pos_enc(int pos, int d) {
    const int i2 = d & ~1;  // 2*(d/2)
    const float freq = expf(-(float)i2 * (9.210340371976184f / 512.f)); // ln(10000)/D
    const float ang = (float)pos * freq;
    return (d & 1) ? cosf(ang) : sinf(ang);
}

__global__ __launch_bounds__(512) void embed_src_kernel(
    const float* __restrict__ x, const float* __restrict__ w,
    const float* __restrict__ b, float* __restrict__ h)
{
    const int token = blockIdx.x;         // 0..B*S-1
    const int d = threadIdx.x;            // 0..511
    const int s = token % Ssz;
    const float x0 = x[token * 2 + 0], x1 = x[token * 2 + 1];
    h[(size_t)token * Dsz + d] = x0 * w[d] + x1 * w[Dsz + d] + b[d] + pos_enc(s, d);
}

__global__ __launch_bounds__(512) void embed_tgt_kernel(
    const float* __restrict__ y, const float* __restrict__ w,
    const float* __restrict__ b, float* __restrict__ dd)
{
    const int token = blockIdx.x;         // 0..B*T-1
    const int d = threadIdx.x;
    const int bb = token / Tsz, t = token % Tsz;
    const float val = (t == 0) ? 0.f : y[bb * Tsz + (t - 1)];
    dd[(size_t)token * Dsz + d] = val * w[d] + b[d] + pos_enc(t, d);
}

// ---------------- final projection D -> 1 ----------------------------------------
__global__ __launch_bounds__(128) void out_proj_kernel(
    const float* __restrict__ dd, const float* __restrict__ w,
    const float* __restrict__ b, float* __restrict__ out)
{
    const int token = blockIdx.x;
    const int tid = threadIdx.x;
    const int lane = tid & 31, warp = tid >> 5;
    float s = 0.f;
    for (int i = tid; i < Dsz; i += 128)
        s += dd[(size_t)token * Dsz + i] * w[i];
    s = warpSum(s);
    __shared__ float sm[4];
    if (lane == 0) sm[warp] = s;
    __syncthreads();
    if (tid == 0) out[token] = sm[0] + sm[1] + sm[2] + sm[3] + b[0];
}

// ---------------- host orchestration --------------------------------------------
extern "C" void kernel_launch(void* const* d_in, const int* in_sizes, int n_in,
                              void* d_out, int out_size)
{
    const float* x          = (const float*)d_in[0];
    const float* y          = (const float*)d_in[1];
    const float* src_w      = (const float*)d_in[2];
    const float* src_b      = (const float*)d_in[3];
    const float* tgt_w      = (const float*)d_in[4];
    const float* tgt_b      = (const float*)d_in[5];
    const float* enc_attn_w = (const float*)d_in[6];
    const float* enc_attn_b = (const float*)d_in[7];
    const float* enc_ffn_w1 = (const float*)d_in[8];
    const float* enc_ffn_b1 = (const float*)d_in[9];
    const float* enc_ffn_w2 = (const float*)d_in[10];
    const float* enc_ffn_b2 = (const float*)d_in[11];
    const float* enc_ln_s   = (const float*)d_in[12];
    const float* enc_ln_b   = (const float*)d_in[13];
    const float* dec_self_w = (const float*)d_in[14];
    const float* dec_self_b = (const float*)d_in[15];
    const float* dec_cross_w= (const float*)d_in[16];
    const float* dec_cross_b= (const float*)d_in[17];
    const float* dec_ffn_w1 = (const float*)d_in[18];
    const float* dec_ffn_b1 = (const float*)d_in[19];
    const float* dec_ffn_w2 = (const float*)d_in[20];
    const float* dec_ffn_b2 = (const float*)d_in[21];
    const float* dec_ln_s   = (const float*)d_in[22];
    const float* dec_ln_b   = (const float*)d_in[23];
    const float* out_w      = (const float*)d_in[24];
    const float* out_b      = (const float*)d_in[25];

    float *h, *tmp, *q, *k, *v, *ffn, *dd, *dq, *dtmp;
    cudaGetSymbolAddress((void**)&h,    g_h);
    cudaGetSymbolAddress((void**)&tmp,  g_tmp);
    cudaGetSymbolAddress((void**)&q,    g_q);
    cudaGetSymbolAddress((void**)&k,    g_k);
    cudaGetSymbolAddress((void**)&v,    g_v);
    cudaGetSymbolAddress((void**)&ffn,  g_ffn);
    cudaGetSymbolAddress((void**)&dd,   g_d);
    cudaGetSymbolAddress((void**)&dq,   g_dq);
    cudaGetSymbolAddress((void**)&dtmp, g_dtmp);

    const int Me = Bsz * Ssz;   // 16384
    const int Md = Bsz * Tsz;   // 5760
    const size_t DD = (size_t)Dsz * Dsz;

    dim3 blk(256);
    dim3 gE_D(Dsz / 128, Me / 128);
    dim3 gE_F(Fsz / 128, Me / 128);
    dim3 gD_D(Dsz / 128, Md / 128);
    dim3 gD_F(Fsz / 128, Md / 128);

    // ===== encoder =====
    embed_src_kernel<<<Me, 512>>>(x, src_w, src_b, h);
    for (int l = 0; l < Lsz; l++) {
        const float* w  = enc_attn_w + (size_t)l * 4 * DD;
        const float* wb = enc_attn_b + (size_t)l * 4 * Dsz;
        sgemm_bias<<<gE_D, blk>>>(h, w,          wb,          q, Me, Dsz, Dsz, 0);
        sgemm_bias<<<gE_D, blk>>>(h, w + DD,     wb + Dsz,    k, Me, Dsz, Dsz, 0);
        sgemm_bias<<<gE_D, blk>>>(h, w + 2*DD,   wb + 2*Dsz,  v, Me, Dsz, Dsz, 0);
        attn_kernel<<<dim3(Ssz, Hsz, Bsz), 128>>>(q, k, v, tmp, Ssz, Ssz, 0);
        sgemm_bias<<<gE_D, blk>>>(tmp, w + 3*DD, wb + 3*Dsz,  q, Me, Dsz, Dsz, 0);
        add_ln_kernel<<<Me, 128>>>(h, q, enc_ln_s + (size_t)(l*2)*Dsz,
                                         enc_ln_b + (size_t)(l*2)*Dsz);
        sgemm_bias<<<gE_F, blk>>>(h, enc_ffn_w1 + (size_t)l*Dsz*Fsz,
                                  enc_ffn_b1 + (size_t)l*Fsz, ffn, Me, Fsz, Dsz, 1);
        sgemm_bias<<<gE_D, blk>>>(ffn, enc_ffn_w2 + (size_t)l*Fsz*Dsz,
                                  enc_ffn_b2 + (size_t)l*Dsz, tmp, Me, Dsz, Fsz, 0);
        add_ln_kernel<<<Me, 128>>>(h, tmp, enc_ln_s + (size_t)(l*2+1)*Dsz,
                                           enc_ln_b + (size_t)(l*2+1)*Dsz);
    }

    // ===== decoder =====
    embed_tgt_kernel<<<Md, 512>>>(y, tgt_w, tgt_b, dd);
    for (int l = 0; l < Lsz; l++) {
        // self-attention (causal)
        const float* w  = dec_self_w + (size_t)l * 4 * DD;
        const float* wb = dec_self_b + (size_t)l * 4 * Dsz;
        sgemm_bias<<<gD_D, blk>>>(dd, w,        wb,         dq, Md, Dsz, Dsz, 0);
        sgemm_bias<<<gD_D, blk>>>(dd, w + DD,   wb + Dsz,   k,  Md, Dsz, Dsz, 0);
        sgemm_bias<<<gD_D, blk>>>(dd, w + 2*DD, wb + 2*Dsz, v,  Md, Dsz, Dsz, 0);
        attn_kernel<<<dim3(Tsz, Hsz, Bsz), 128>>>(dq, k, v, dtmp, Tsz, Tsz, 1);
        sgemm_bias<<<gD_D, blk>>>(dtmp, w + 3*DD, wb + 3*Dsz, dq, Md, Dsz, Dsz, 0);
        add_ln_kernel<<<Md, 128>>>(dd, dq, dec_ln_s + (size_t)(l*3)*Dsz,
                                           dec_ln_b + (size_t)(l*3)*Dsz);
        // cross-attention
        const float* cw  = dec_cross_w + (size_t)l * 4 * DD;
        const float* cwb = dec_cross_b + (size_t)l * 4 * Dsz;
        sgemm_bias<<<gD_D, blk>>>(dd, cw,        cwb,         dq, Md, Dsz, Dsz, 0);
        sgemm_bias<<<gE_D, blk>>>(h,  cw + DD,   cwb + Dsz,   k,  Me, Dsz, Dsz, 0);
        sgemm_bias<<<gE_D, blk>>>(h,  cw + 2*DD, cwb + 2*Dsz, v,  Me, Dsz, Dsz, 0);
        attn_kernel<<<dim3(Tsz, Hsz, Bsz), 128>>>(dq, k, v, dtmp, Tsz, Ssz, 0);
        sgemm_bias<<<gD_D, blk>>>(dtmp, cw + 3*DD, cwb + 3*Dsz, dq, Md, Dsz, Dsz, 0);
        add_ln_kernel<<<Md, 128>>>(dd, dq, dec_ln_s + (size_t)(l*3+1)*Dsz,
                                           dec_ln_b + (size_t)(l*3+1)*Dsz);
        // FFN
        sgemm_bias<<<gD_F, blk>>>(dd, dec_ffn_w1 + (size_t)l*Dsz*Fsz,
                                  dec_ffn_b1 + (size_t)l*Fsz, ffn, Md, Fsz, Dsz, 1);
        sgemm_bias<<<gD_D, blk>>>(ffn, dec_ffn_w2 + (size_t)l*Fsz*Dsz,
                                  dec_ffn_b2 + (size_t)l*Dsz, dtmp, Md, Dsz, Fsz, 0);
        add_ln_kernel<<<Md, 128>>>(dd, dtmp, dec_ln_s + (size_t)(l*3+2)*Dsz,
                                             dec_ln_b + (size_t)(l*3+2)*Dsz);
    }

    // ===== output head =====
    out_proj_kernel<<<Md, 128>>>(dd, out_w, out_b, (float*)d_out);
}

// round 2
// speedup vs baseline: 4.9516x; 4.9516x over previous
#include <cuda_runtime.h>
#include <math.h>
#include <stdint.h>

#define Bsz 32
#define Ssz 512
#define Tsz 180
#define Dsz 512
#define Fsz 2048
#define Lsz 6
#define Hsz 8
#define DHsz 64
#define QT 32

// ---------------- scratch buffers ----------------
__device__ float g_h   [Bsz*Ssz*Dsz];
__device__ float g_tmp [Bsz*Ssz*Dsz];
__device__ float g_q   [Bsz*Ssz*Dsz];
__device__ float g_k   [Bsz*Ssz*Dsz];
__device__ float g_v   [Bsz*Ssz*Dsz];
__device__ float g_ffn [Bsz*Ssz*Fsz];
__device__ float g_d   [Bsz*Tsz*Dsz];
__device__ float g_dq  [Bsz*Tsz*Dsz];
__device__ float g_dtmp[Bsz*Tsz*Dsz];

__device__ __forceinline__ float warpSum(float v) {
    #pragma unroll
    for (int o = 16; o; o >>= 1) v += __shfl_xor_sync(0xffffffffu, v, o);
    return v;
}
__device__ __forceinline__ float warpMax(float v) {
    #pragma unroll
    for (int o = 16; o; o >>= 1) v = fmaxf(v, __shfl_xor_sync(0xffffffffu, v, o));
    return v;
}

__device__ __forceinline__ uint4 cvt_tf32x4(float4 v) {
    uint4 u;
    asm("cvt.rna.tf32.f32 %0, %1;" : "=r"(u.x) : "f"(v.x));
    asm("cvt.rna.tf32.f32 %0, %1;" : "=r"(u.y) : "f"(v.y));
    asm("cvt.rna.tf32.f32 %0, %1;" : "=r"(u.z) : "f"(v.z));
    asm("cvt.rna.tf32.f32 %0, %1;" : "=r"(u.w) : "f"(v.w));
    return u;
}

#define MMA_TF32(c, a, b) \
    asm volatile("mma.sync.aligned.m16n8k8.row.col.f32.tf32.tf32.f32 " \
        "{%0,%1,%2,%3}, {%4,%5,%6,%7}, {%8,%9}, {%0,%1,%2,%3};" \
        : "+f"((c)[0]), "+f"((c)[1]), "+f"((c)[2]), "+f"((c)[3]) \
        : "r"((a)[0]), "r"((a)[1]), "r"((a)[2]), "r"((a)[3]), \
          "r"((b)[0]), "r"((b)[1]))

// ---------------- TF32 tensor-core GEMM -----------------------------------------
// C[M,N] = A[M,K] @ B[K,N] + bias[N], optional ReLU.
// BM=BN=128, BK=16, 256 threads (8 warps, 2x4), warp tile 64x32, mma m16n8k8.
__global__ __launch_bounds__(256, 2) void gemm_tf32(
    const float* __restrict__ A, const float* __restrict__ B,
    const float* __restrict__ bias, float* __restrict__ C,
    int M, int N, int K, int doRelu)
{
    __shared__ uint32_t As[2][128 * 20];   // [m][k] stride 20 (pad)
    __shared__ uint32_t Bs[2][16 * 136];   // [k][n] stride 136 (pad)

    const int tid  = threadIdx.x;
    const int lane = tid & 31;
    const int warp = tid >> 5;
    const int g  = lane >> 2;       // 0..7
    const int t4 = lane & 3;        // 0..3
    const int wm = (warp >> 2) << 6;  // 0 or 64
    const int wn = (warp & 3) << 5;   // 0,32,64,96
    const int bm = blockIdx.y << 7;
    const int bn = blockIdx.x << 7;

    // staging indices
    const int ar = tid >> 2;          // 0..63
    const int ac = (tid & 3) << 2;    // 0,4,8,12
    const int br = tid >> 5;          // 0..7
    const int bc = lane << 2;         // 0..124

    const float* Ap0 = A + (size_t)(bm + ar) * K + ac;
    const float* Ap1 = A + (size_t)(bm + ar + 64) * K + ac;
    const float* Bp0 = B + (size_t)br * N + bn + bc;
    const float* Bp1 = B + (size_t)(br + 8) * N + bn + bc;

    float acc[4][4][4] = {};

    // prologue: stage k-tile 0
    float4 ra0 = *(const float4*)Ap0;
    float4 ra1 = *(const float4*)Ap1;
    float4 rb0 = *(const float4*)Bp0;
    float4 rb1 = *(const float4*)Bp1;
    *(uint4*)&As[0][ar * 20 + ac]        = cvt_tf32x4(ra0);
    *(uint4*)&As[0][(ar + 64) * 20 + ac] = cvt_tf32x4(ra1);
    *(uint4*)&Bs[0][br * 136 + bc]       = cvt_tf32x4(rb0);
    *(uint4*)&Bs[0][(br + 8) * 136 + bc] = cvt_tf32x4(rb1);
    __syncthreads();

    int buf = 0;
    for (int k0 = 16; k0 < K; k0 += 16) {
        // prefetch next tile
        ra0 = *(const float4*)(Ap0 + k0);
        ra1 = *(const float4*)(Ap1 + k0);
        rb0 = *(const float4*)(Bp0 + (size_t)k0 * N);
        rb1 = *(const float4*)(Bp1 + (size_t)k0 * N);

        // compute current buffer
        #pragma unroll
        for (int kk = 0; kk < 2; kk++) {
            uint32_t af[4][4], bf[4][2];
            #pragma unroll
            for (int mt = 0; mt < 4; mt++) {
                int base = (wm + mt * 16 + g) * 20 + kk * 8 + t4;
                af[mt][0] = As[buf][base];
                af[mt][1] = As[buf][base + 160];
                af[mt][2] = As[buf][base + 4];
                af[mt][3] = As[buf][base + 164];
            }
            #pragma unroll
            for (int nt = 0; nt < 4; nt++) {
                int base = (kk * 8 + t4) * 136 + wn + nt * 8 + g;
                bf[nt][0] = Bs[buf][base];
                bf[nt][1] = Bs[buf][base + 544];
            }
            #pragma unroll
            for (int mt = 0; mt < 4; mt++)
                #pragma unroll
                for (int nt = 0; nt < 4; nt++)
                    MMA_TF32(acc[mt][nt], af[mt], bf[nt]);
        }

        const int nb = buf ^ 1;
        *(uint4*)&As[nb][ar * 20 + ac]        = cvt_tf32x4(ra0);
        *(uint4*)&As[nb][(ar + 64) * 20 + ac] = cvt_tf32x4(ra1);
        *(uint4*)&Bs[nb][br * 136 + bc]       = cvt_tf32x4(rb0);
        *(uint4*)&Bs[nb][(br + 8) * 136 + bc] = cvt_tf32x4(rb1);
        __syncthreads();
        buf = nb;
    }
    // last tile
    #pragma unroll
    for (int kk = 0; kk < 2; kk++) {
        uint32_t af[4][4], bf[4][2];
        #pragma unroll
        for (int mt = 0; mt < 4; mt++) {
            int base = (wm + mt * 16 + g) * 20 + kk * 8 + t4;
            af[mt][0] = As[buf][base];
            af[mt][1] = As[buf][base + 160];
            af[mt][2] = As[buf][base + 4];
            af[mt][3] = As[buf][base + 164];
        }
        #pragma unroll
        for (int nt = 0; nt < 4; nt++) {
            int base = (kk * 8 + t4) * 136 + wn + nt * 8 + g;
            bf[nt][0] = Bs[buf][base];
            bf[nt][1] = Bs[buf][base + 544];
        }
        #pragma unroll
        for (int mt = 0; mt < 4; mt++)
            #pragma unroll
            for (int nt = 0; nt < 4; nt++)
                MMA_TF32(acc[mt][nt], af[mt], bf[nt]);
    }

    // epilogue: bias (+relu), float2 stores
    #pragma unroll
    for (int mt = 0; mt < 4; mt++) {
        const int gm = bm + wm + mt * 16 + g;
        #pragma unroll
        for (int nt = 0; nt < 4; nt++) {
            const int gn = bn + wn + nt * 8 + (t4 << 1);
            const float b0v = bias[gn], b1v = bias[gn + 1];
            float2 o0 = make_float2(acc[mt][nt][0] + b0v, acc[mt][nt][1] + b1v);
            float2 o1 = make_float2(acc[mt][nt][2] + b0v, acc[mt][nt][3] + b1v);
            if (doRelu) {
                o0.x = fmaxf(o0.x, 0.f); o0.y = fmaxf(o0.y, 0.f);
                o1.x = fmaxf(o1.x, 0.f); o1.y = fmaxf(o1.y, 0.f);
            }
            *(float2*)(C + (size_t)gm * N + gn)       = o0;
            *(float2*)(C + (size_t)(gm + 8) * N + gn) = o1;
        }
    }
}

// ---------------- tiled attention ------------------------------------------------
// Block = (qtile of 32, h, b). 256 threads. Two-pass: scores in smem, softmax, PV.
__global__ __launch_bounds__(256) void attn_tile(
    const float* __restrict__ Q, const float* __restrict__ K,
    const float* __restrict__ V, float* __restrict__ O,
    int Sq, int Sk, int Skc, int causal)
{
    extern __shared__ float smf[];
    float* Qs = smf;                 // QT x 68
    float* Ks = Qs + QT * 68;        // 64 x 68 (K^T in phase1, V in phase3)
    float* sc = Ks + 64 * 68;        // QT x Skc

    const int tid = threadIdx.x;
    const int qtile = blockIdx.x, h = blockIdx.y, b = blockIdx.z;
    const int qbase = qtile * QT;
    const size_t hoff = (size_t)h * DHsz;

    const int tq = (tid >> 4) << 1;   // 0..30
    const int tk = (tid & 15) << 2;   // 0..60

    // init scores to -inf
    for (int i = tid; i < QT * Skc; i += 256) sc[i] = -1e30f;

    // load Q tile
    {
        const int qrow = tid >> 4;           // 0..15
        const int d4 = (tid & 15) << 2;
        #pragma unroll
        for (int p = 0; p < 2; p++) {
            const int qq = qrow + p * 16;
            const int qg = qbase + qq;
            float4 v4 = (qg < Sq)
                ? *(const float4*)(Q + (size_t)(b * Sq + qg) * Dsz + hoff + d4)
                : make_float4(0.f, 0.f, 0.f, 0.f);
            *(float4*)&Qs[qq * 68 + d4] = v4;
        }
    }
    __syncthreads();

    const int qend = qbase + QT - 1;

    // ---- phase 1: scores ----
    for (int c0 = 0; c0 < Sk; c0 += 64) {
        if (causal && c0 > qend) break;
        {
            const int kl = tid >> 4;
            const int d4 = (tid & 15) << 2;
            #pragma unroll
            for (int p = 0; p < 4; p++) {
                const int kk = kl + p * 16;
                const int kg = c0 + kk;
                float4 v4 = (kg < Sk)
                    ? *(const float4*)(K + (size_t)(b * Sk + kg) * Dsz + hoff + d4)
                    : make_float4(0.f, 0.f, 0.f, 0.f);
                Ks[(d4 + 0) * 68 + kk] = v4.x;
                Ks[(d4 + 1) * 68 + kk] = v4.y;
                Ks[(d4 + 2) * 68 + kk] = v4.z;
                Ks[(d4 + 3) * 68 + kk] = v4.w;
            }
        }
        __syncthreads();

        float a0[4] = {0.f, 0.f, 0.f, 0.f};
        float a1[4] = {0.f, 0.f, 0.f, 0.f};
        #pragma unroll 8
        for (int d = 0; d < 64; d++) {
            const float q0 = Qs[tq * 68 + d];
            const float q1 = Qs[(tq + 1) * 68 + d];
            const float4 k4 = *(const float4*)&Ks[d * 68 + tk];
            a0[0] = fmaf(q0, k4.x, a0[0]); a0[1] = fmaf(q0, k4.y, a0[1]);
            a0[2] = fmaf(q0, k4.z, a0[2]); a0[3] = fmaf(q0, k4.w, a0[3]);
            a1[0] = fmaf(q1, k4.x, a1[0]); a1[1] = fmaf(q1, k4.y, a1[1]);
            a1[2] = fmaf(q1, k4.z, a1[2]); a1[3] = fmaf(q1, k4.w, a1[3]);
        }
        #pragma unroll
        for (int j = 0; j < 4; j++) {
            const int kg = c0 + tk + j;
            if (kg < Sk) {
                if (!causal || kg <= qbase + tq)
                    sc[tq * Skc + kg] = a0[j] * 0.125f;
                if (!causal || kg <= qbase + tq + 1)
                    sc[(tq + 1) * Skc + kg] = a1[j] * 0.125f;
            }
        }
        __syncthreads();
    }
    __syncthreads();

    // ---- phase 2: softmax (warp per row) ----
    {
        const int lane = tid & 31, warp = tid >> 5;
        for (int r = warp; r < QT; r += 8) {
            float* row = sc + r * Skc;
            float m = -1e30f;
            for (int i = lane; i < Skc; i += 32) m = fmaxf(m, row[i]);
            m = warpMax(m);
            float s = 0.f;
            for (int i = lane; i < Skc; i += 32) {
                float e = __expf(row[i] - m);
                row[i] = e;
                s += e;
            }
            s = warpSum(s);
            const float inv = 1.f / s;
            for (int i = lane; i < Skc; i += 32) row[i] *= inv;
        }
    }
    __syncthreads();

    // ---- phase 3: P @ V ----
    float o0[4] = {0.f, 0.f, 0.f, 0.f};
    float o1[4] = {0.f, 0.f, 0.f, 0.f};
    for (int c0 = 0; c0 < Sk; c0 += 64) {
        if (causal && c0 > qend) break;
        {
            const int kl = tid >> 4;
            const int d4 = (tid & 15) << 2;
            #pragma unroll
            for (int p = 0; p < 4; p++) {
                const int kk = kl + p * 16;
                const int kg = c0 + kk;
                float4 v4 = (kg < Sk)
                    ? *(const float4*)(V + (size_t)(b * Sk + kg) * Dsz + hoff + d4)
                    : make_float4(0.f, 0.f, 0.f, 0.f);
                *(float4*)&Ks[kk * 68 + d4] = v4;
            }
        }
        __syncthreads();
        #pragma unroll 8
        for (int key = 0; key < 64; key++) {
            const float p0 = sc[tq * Skc + c0 + key];
            const float p1 = sc[(tq + 1) * Skc + c0 + key];
            const float4 v4 = *(const float4*)&Ks[key * 68 + tk];
            o0[0] = fmaf(p0, v4.x, o0[0]); o0[1] = fmaf(p0, v4.y, o0[1]);
            o0[2] = fmaf(p0, v4.z, o0[2]); o0[3] = fmaf(p0, v4.w, o0[3]);
            o1[0] = fmaf(p1, v4.x, o1[0]); o1[1] = fmaf(p1, v4.y, o1[1]);
            o1[2] = fmaf(p1, v4.z, o1[2]); o1[3] = fmaf(p1, v4.w, o1[3]);
        }
        __syncthreads();
    }
    // write O
    {
        const int qg0 = qbase + tq;
        if (qg0 < Sq)
            *(float4*)(O + (size_t)(b * Sq + qg0) * Dsz + hoff + tk) =
                make_float4(o0[0], o0[1], o0[2], o0[3]);
        const int qg1 = qg0 + 1;
        if (qg1 < Sq)
            *(float4*)(O + (size_t)(b * Sq + qg1) * Dsz + hoff + tk) =
                make_float4(o1[0], o1[1], o1[2], o1[3]);
    }
}

// ---------------- residual + LayerNorm -------------------------------------------
__global__ __launch_bounds__(128) void add_ln_kernel(
    float* __restrict__ h, const float* __restrict__ r,
    const float* __restrict__ scale, const float* __restrict__ bias)
{
    const int row = blockIdx.x;
    const int tid = threadIdx.x;
    const int lane = tid & 31, warp = tid >> 5;
    float* hp = h + (size_t)row * Dsz;
    const float* rp = r + (size_t)row * Dsz;

    float4 hv = *(const float4*)(hp + tid * 4);
    float4 rv = *(const float4*)(rp + tid * 4);
    float v0 = hv.x + rv.x, v1 = hv.y + rv.y, v2 = hv.z + rv.z, v3 = hv.w + rv.w;

    float sum = v0 + v1 + v2 + v3;
    float sq  = v0*v0 + v1*v1 + v2*v2 + v3*v3;
    sum = warpSum(sum); sq = warpSum(sq);

    __shared__ float s1[4], s2[4];
    if (lane == 0) { s1[warp] = sum; s2[warp] = sq; }
    __syncthreads();
    sum = s1[0] + s1[1] + s1[2] + s1[3];
    sq  = s2[0] + s2[1] + s2[2] + s2[3];

    const float mu = sum * (1.f / Dsz);
    const float var = sq * (1.f / Dsz) - mu * mu;
    const float rs = rsqrtf(var + 1e-5f);

    float4 sc4 = *(const float4*)(scale + tid * 4);
    float4 bi4 = *(const float4*)(bias + tid * 4);
    float4 o;
    o.x = (v0 - mu) * rs * sc4.x + bi4.x;
    o.y = (v1 - mu) * rs * sc4.y + bi4.y;
    o.z = (v2 - mu) * rs * sc4.z + bi4.z;
    o.w = (v3 - mu) * rs * sc4.w + bi4.w;
    *(float4*)(hp + tid * 4) = o;
}

// ---------------- embeddings ------------------------------------------------------
__device__ __forceinline__ float pos_enc(int pos, int d) {
    const int i2 = d & ~1;
    const float freq = expf(-(float)i2 * (9.210340371976184f / 512.f));
    const float ang = (float)pos * freq;
    return (d & 1) ? cosf(ang) : sinf(ang);
}

__global__ __launch_bounds__(512) void embed_src_kernel(
    const float* __restrict__ x, const float* __restrict__ w,
    const float* __restrict__ b, float* __restrict__ h)
{
    const int token = blockIdx.x;
    const int d = threadIdx.x;
    const int s = token % Ssz;
    const float x0 = x[token * 2 + 0], x1 = x[token * 2 + 1];
    h[(size_t)token * Dsz + d] = x0 * w[d] + x1 * w[Dsz + d] + b[d] + pos_enc(s, d);
}

__global__ __launch_bounds__(512) void embed_tgt_kernel(
    const float* __restrict__ y, const float* __restrict__ w,
    const float* __restrict__ b, float* __restrict__ dd)
{
    const int token = blockIdx.x;
    const int d = threadIdx.x;
    const int bb = token / Tsz, t = token % Tsz;
    const float val = (t == 0) ? 0.f : y[bb * Tsz + (t - 1)];
    dd[(size_t)token * Dsz + d] = val * w[d] + b[d] + pos_enc(t, d);
}

// ---------------- final projection -------------------------------------------------
__global__ __launch_bounds__(128) void out_proj_kernel(
    const float* __restrict__ dd, const float* __restrict__ w,
    const float* __restrict__ b, float* __restrict__ out)
{
    const int token = blockIdx.x;
    const int tid = threadIdx.x;
    const int lane = tid & 31, warp = tid >> 5;
    float s = 0.f;
    for (int i = tid; i < Dsz; i += 128)
        s += dd[(size_t)token * Dsz + i] * w[i];
    s = warpSum(s);
    __shared__ float smr[4];
    if (lane == 0) smr[warp] = s;
    __syncthreads();
    if (tid == 0) out[token] = smr[0] + smr[1] + smr[2] + smr[3] + b[0];
}

// ---------------- host orchestration ----------------------------------------------
extern "C" void kernel_launch(void* const* d_in, const int* in_sizes, int n_in,
                              void* d_out, int out_size)
{
    const float* x          = (const float*)d_in[0];
    const float* y          = (const float*)d_in[1];
    const float* src_w      = (const float*)d_in[2];
    const float* src_b      = (const float*)d_in[3];
    const float* tgt_w      = (const float*)d_in[4];
    const float* tgt_b      = (const float*)d_in[5];
    const float* enc_attn_w = (const float*)d_in[6];
    const float* enc_attn_b = (const float*)d_in[7];
    const float* enc_ffn_w1 = (const float*)d_in[8];
    const float* enc_ffn_b1 = (const float*)d_in[9];
    const float* enc_ffn_w2 = (const float*)d_in[10];
    const float* enc_ffn_b2 = (const float*)d_in[11];
    const float* enc_ln_s   = (const float*)d_in[12];
    const float* enc_ln_b   = (const float*)d_in[13];
    const float* dec_self_w = (const float*)d_in[14];
    const float* dec_self_b = (const float*)d_in[15];
    const float* dec_cross_w= (const float*)d_in[16];
    const float* dec_cross_b= (const float*)d_in[17];
    const float* dec_ffn_w1 = (const float*)d_in[18];
    const float* dec_ffn_b1 = (const float*)d_in[19];
    const float* dec_ffn_w2 = (const float*)d_in[20];
    const float* dec_ffn_b2 = (const float*)d_in[21];
    const float* dec_ln_s   = (const float*)d_in[22];
    const float* dec_ln_b   = (const float*)d_in[23];
    const float* out_w      = (const float*)d_in[24];
    const float* out_b      = (const float*)d_in[25];

    float *h, *tmp, *q, *k, *v, *ffn, *dd, *dq, *dtmp;
    cudaGetSymbolAddress((void**)&h,    g_h);
    cudaGetSymbolAddress((void**)&tmp,  g_tmp);
    cudaGetSymbolAddress((void**)&q,    g_q);
    cudaGetSymbolAddress((void**)&k,    g_k);
    cudaGetSymbolAddress((void**)&v,    g_v);
    cudaGetSymbolAddress((void**)&ffn,  g_ffn);
    cudaGetSymbolAddress((void**)&dd,   g_d);
    cudaGetSymbolAddress((void**)&dq,   g_dq);
    cudaGetSymbolAddress((void**)&dtmp, g_dtmp);

    const int Me = Bsz * Ssz;   // 16384
    const int Md = Bsz * Tsz;   // 5760
    const size_t DD = (size_t)Dsz * Dsz;

    // attention smem sizes
    const int SkcE = 512;  // encoder/cross key span (padded to 64)
    const int SkcD = 192;  // decoder self
    const int smemE = (QT * 68 + 64 * 68 + QT * SkcE) * 4;
    const int smemD = (QT * 68 + 64 * 68 + QT * SkcD) * 4;
    cudaFuncSetAttribute(attn_tile, cudaFuncAttributeMaxDynamicSharedMemorySize, smemE);

    const int qtE = Ssz / QT;                 // 16
    const int qtD = (Tsz + QT - 1) / QT;      // 6

    dim3 blk(256);
    dim3 gE_D(Dsz / 128, Me / 128);
    dim3 gE_F(Fsz / 128, Me / 128);
    dim3 gD_D(Dsz / 128, Md / 128);
    dim3 gD_F(Fsz / 128, Md / 128);

    // ===== encoder =====
    embed_src_kernel<<<Me, 512>>>(x, src_w, src_b, h);
    for (int l = 0; l < Lsz; l++) {
        const float* w  = enc_attn_w + (size_t)l * 4 * DD;
        const float* wb = enc_attn_b + (size_t)l * 4 * Dsz;
        gemm_tf32<<<gE_D, blk>>>(h, w,          wb,          q, Me, Dsz, Dsz, 0);
        gemm_tf32<<<gE_D, blk>>>(h, w + DD,     wb + Dsz,    k, Me, Dsz, Dsz, 0);
        gemm_tf32<<<gE_D, blk>>>(h, w + 2*DD,   wb + 2*Dsz,  v, Me, Dsz, Dsz, 0);
        attn_tile<<<dim3(qtE, Hsz, Bsz), 256, smemE>>>(q, k, v, tmp, Ssz, Ssz, SkcE, 0);
        gemm_tf32<<<gE_D, blk>>>(tmp, w + 3*DD, wb + 3*Dsz,  q, Me, Dsz, Dsz, 0);
        add_ln_kernel<<<Me, 128>>>(h, q, enc_ln_s + (size_t)(l*2)*Dsz,
                                         enc_ln_b + (size_t)(l*2)*Dsz);
        gemm_tf32<<<gE_F, blk>>>(h, enc_ffn_w1 + (size_t)l*Dsz*Fsz,
                                 enc_ffn_b1 + (size_t)l*Fsz, ffn, Me, Fsz, Dsz, 1);
        gemm_tf32<<<gE_D, blk>>>(ffn, enc_ffn_w2 + (size_t)l*Fsz*Dsz,
                                 enc_ffn_b2 + (size_t)l*Dsz, tmp, Me, Dsz, Fsz, 0);
        add_ln_kernel<<<Me, 128>>>(h, tmp, enc_ln_s + (size_t)(l*2+1)*Dsz,
                                           enc_ln_b + (size_t)(l*2+1)*Dsz);
    }

    // ===== decoder =====
    embed_tgt_kernel<<<Md, 512>>>(y, tgt_w, tgt_b, dd);
    for (int l = 0; l < Lsz; l++) {
        const float* w  = dec_self_w + (size_t)l * 4 * DD;
        const float* wb = dec_self_b + (size_t)l * 4 * Dsz;
        gemm_tf32<<<gD_D, blk>>>(dd, w,        wb,         dq, Md, Dsz, Dsz, 0);
        gemm_tf32<<<gD_D, blk>>>(dd, w + DD,   wb + Dsz,   k,  Md, Dsz, Dsz, 0);
        gemm_tf32<<<gD_D, blk>>>(dd, w + 2*DD, wb + 2*Dsz, v,  Md, Dsz, Dsz, 0);
        attn_tile<<<dim3(qtD, Hsz, Bsz), 256, smemD>>>(dq, k, v, dtmp, Tsz, Tsz, SkcD, 1);
        gemm_tf32<<<gD_D, blk>>>(dtmp, w + 3*DD, wb + 3*Dsz, dq, Md, Dsz, Dsz, 0);
        add_ln_kernel<<<Md, 128>>>(dd, dq, dec_ln_s + (size_t)(l*3)*Dsz,
                                           dec_ln_b + (size_t)(l*3)*Dsz);

        const float* cw  = dec_cross_w + (size_t)l * 4 * DD;
        const float* cwb = dec_cross_b + (size_t)l * 4 * Dsz;
        gemm_tf32<<<gD_D, blk>>>(dd, cw,        cwb,         dq, Md, Dsz, Dsz, 0);
        gemm_tf32<<<gE_D, blk>>>(h,  cw + DD,   cwb + Dsz,   k,  Me, Dsz, Dsz, 0);
        gemm_tf32<<<gE_D, blk>>>(h,  cw + 2*DD, cwb + 2*Dsz, v,  Me, Dsz, Dsz, 0);
        attn_tile<<<dim3(qtD, Hsz, Bsz), 256, smemE>>>(dq, k, v, dtmp, Tsz, Ssz, SkcE, 0);
        gemm_tf32<<<gD_D, blk>>>(dtmp, cw + 3*DD, cwb + 3*Dsz, dq, Md, Dsz, Dsz, 0);
        add_ln_kernel<<<Md, 128>>>(dd, dq, dec_ln_s + (size_t)(l*3+1)*Dsz,
                                           dec_ln_b + (size_t)(l*3+1)*Dsz);

        gemm_tf32<<<gD_F, blk>>>(dd, dec_ffn_w1 + (size_t)l*Dsz*Fsz,
                                 dec_ffn_b1 + (size_t)l*Fsz, ffn, Md, Fsz, Dsz, 1);
        gemm_tf32<<<gD_D, blk>>>(ffn, dec_ffn_w2 + (size_t)l*Fsz*Dsz,
                                 dec_ffn_b2 + (size_t)l*Dsz, dtmp, Md, Dsz, Fsz, 0);
        add_ln_kernel<<<Md, 128>>>(dd, dtmp, dec_ln_s + (size_t)(l*3+2)*Dsz,
                                             dec_ln_b + (size_t)(l*3+2)*Dsz);
    }

    out_proj_kernel<<<Md, 128>>>(dd, out_w, out_b, (float*)d_out);
}

// round 3
// speedup vs baseline: 4.9606x; 1.0018x over previous
#include <cuda_runtime.h>
#include <math.h>
#include <stdint.h>

#define Bsz 32
#define Ssz 512
#define Tsz 180
#define Dsz 512
#define Fsz 2048
#define Lsz 6
#define Hsz 8
#define DHsz 64
#define QT 32

// ---------------- scratch buffers ----------------
__device__ float g_h   [Bsz*Ssz*Dsz];
__device__ float g_tmp [Bsz*Ssz*Dsz];
__device__ float g_q   [Bsz*Ssz*Dsz];
__device__ float g_k   [Bsz*Ssz*Dsz];
__device__ float g_v   [Bsz*Ssz*Dsz];
__device__ float g_ffn [Bsz*Ssz*Fsz];
__device__ float g_d   [Bsz*Tsz*Dsz];
__device__ float g_dq  [Bsz*Tsz*Dsz];
__device__ float g_dtmp[Bsz*Tsz*Dsz];

__device__ __forceinline__ float warpSum(float v) {
    #pragma unroll
    for (int o = 16; o; o >>= 1) v += __shfl_xor_sync(0xffffffffu, v, o);
    return v;
}
__device__ __forceinline__ float warpMax(float v) {
    #pragma unroll
    for (int o = 16; o; o >>= 1) v = fmaxf(v, __shfl_xor_sync(0xffffffffu, v, o));
    return v;
}

__device__ __forceinline__ uint4 cvt_tf32x4(float4 v) {
    uint4 u;
    asm("cvt.rna.tf32.f32 %0, %1;" : "=r"(u.x) : "f"(v.x));
    asm("cvt.rna.tf32.f32 %0, %1;" : "=r"(u.y) : "f"(v.y));
    asm("cvt.rna.tf32.f32 %0, %1;" : "=r"(u.z) : "f"(v.z));
    asm("cvt.rna.tf32.f32 %0, %1;" : "=r"(u.w) : "f"(v.w));
    return u;
}

#define MMA_TF32(c, a, b) \
    asm volatile("mma.sync.aligned.m16n8k8.row.col.f32.tf32.tf32.f32 " \
        "{%0,%1,%2,%3}, {%4,%5,%6,%7}, {%8,%9}, {%0,%1,%2,%3};" \
        : "+f"((c)[0]), "+f"((c)[1]), "+f"((c)[2]), "+f"((c)[3]) \
        : "r"((a)[0]), "r"((a)[1]), "r"((a)[2]), "r"((a)[3]), \
          "r"((b)[0]), "r"((b)[1]))

// ---------------- TF32 tensor-core GEMM -----------------------------------------
// C[M,N] = A[M,K] @ B[K,N] + bias[N], optional ReLU.
// BM=BN=128, BK=16, 256 threads (8 warps, 2x4), warp tile 64x32, mma m16n8k8.
__global__ __launch_bounds__(256, 2) void gemm_tf32(
    const float* __restrict__ A, const float* __restrict__ B,
    const float* __restrict__ bias, float* __restrict__ C,
    int M, int N, int K, int doRelu)
{
    __shared__ uint32_t As[2][128 * 20];   // [m][k] stride 20 (pad)
    __shared__ uint32_t Bs[2][16 * 136];   // [k][n] stride 136 (pad)

    const int tid  = threadIdx.x;
    const int lane = tid & 31;
    const int warp = tid >> 5;
    const int g  = lane >> 2;       // 0..7
    const int t4 = lane & 3;        // 0..3
    const int wm = (warp >> 2) << 6;  // 0 or 64
    const int wn = (warp & 3) << 5;   // 0,32,64,96
    const int bm = blockIdx.y << 7;
    const int bn = blockIdx.x << 7;

    // staging indices
    const int ar = tid >> 2;          // 0..63
    const int ac = (tid & 3) << 2;    // 0,4,8,12
    const int br = tid >> 5;          // 0..7
    const int bc = lane << 2;         // 0..124

    const float* Ap0 = A + (size_t)(bm + ar) * K + ac;
    const float* Ap1 = A + (size_t)(bm + ar + 64) * K + ac;
    const float* Bp0 = B + (size_t)br * N + bn + bc;
    const float* Bp1 = B + (size_t)(br + 8) * N + bn + bc;

    float acc[4][4][4] = {};

    // prologue: stage k-tile 0
    float4 ra0 = *(const float4*)Ap0;
    float4 ra1 = *(const float4*)Ap1;
    float4 rb0 = *(const float4*)Bp0;
    float4 rb1 = *(const float4*)Bp1;
    *(uint4*)&As[0][ar * 20 + ac]        = cvt_tf32x4(ra0);
    *(uint4*)&As[0][(ar + 64) * 20 + ac] = cvt_tf32x4(ra1);
    *(uint4*)&Bs[0][br * 136 + bc]       = cvt_tf32x4(rb0);
    *(uint4*)&Bs[0][(br + 8) * 136 + bc] = cvt_tf32x4(rb1);
    __syncthreads();

    int buf = 0;
    for (int k0 = 16; k0 < K; k0 += 16) {
        // prefetch next tile
        ra0 = *(const float4*)(Ap0 + k0);
        ra1 = *(const float4*)(Ap1 + k0);
        rb0 = *(const float4*)(Bp0 + (size_t)k0 * N);
        rb1 = *(const float4*)(Bp1 + (size_t)k0 * N);

        // compute current buffer
        #pragma unroll
        for (int kk = 0; kk < 2; kk++) {
            uint32_t af[4][4], bf[4][2];
            #pragma unroll
            for (int mt = 0; mt < 4; mt++) {
                int base = (wm + mt * 16 + g) * 20 + kk * 8 + t4;
                af[mt][0] = As[buf][base];
                af[mt][1] = As[buf][base + 160];
                af[mt][2] = As[buf][base + 4];
                af[mt][3] = As[buf][base + 164];
            }
            #pragma unroll
            for (int nt = 0; nt < 4; nt++) {
                int base = (kk * 8 + t4) * 136 + wn + nt * 8 + g;
                bf[nt][0] = Bs[buf][base];
                bf[nt][1] = Bs[buf][base + 544];
            }
            #pragma unroll
            for (int mt = 0; mt < 4; mt++)
                #pragma unroll
                for (int nt = 0; nt < 4; nt++)
                    MMA_TF32(acc[mt][nt], af[mt], bf[nt]);
        }

        const int nb = buf ^ 1;
        *(uint4*)&As[nb][ar * 20 + ac]        = cvt_tf32x4(ra0);
        *(uint4*)&As[nb][(ar + 64) * 20 + ac] = cvt_tf32x4(ra1);
        *(uint4*)&Bs[nb][br * 136 + bc]       = cvt_tf32x4(rb0);
        *(uint4*)&Bs[nb][(br + 8) * 136 + bc] = cvt_tf32x4(rb1);
        __syncthreads();
        buf = nb;
    }
    // last tile
    #pragma unroll
    for (int kk = 0; kk < 2; kk++) {
        uint32_t af[4][4], bf[4][2];
        #pragma unroll
        for (int mt = 0; mt < 4; mt++) {
            int base = (wm + mt * 16 + g) * 20 + kk * 8 + t4;
            af[mt][0] = As[buf][base];
            af[mt][1] = As[buf][base + 160];
            af[mt][2] = As[buf][base + 4];
            af[mt][3] = As[buf][base + 164];
        }
        #pragma unroll
        for (int nt = 0; nt < 4; nt++) {
            int base = (kk * 8 + t4) * 136 + wn + nt * 8 + g;
            bf[nt][0] = Bs[buf][base];
            bf[nt][1] = Bs[buf][base + 544];
        }
        #pragma unroll
        for (int mt = 0; mt < 4; mt++)
            #pragma unroll
            for (int nt = 0; nt < 4; nt++)
                MMA_TF32(acc[mt][nt], af[mt], bf[nt]);
    }

    // epilogue: bias (+relu), float2 stores
    #pragma unroll
    for (int mt = 0; mt < 4; mt++) {
        const int gm = bm + wm + mt * 16 + g;
        #pragma unroll
        for (int nt = 0; nt < 4; nt++) {
            const int gn = bn + wn + nt * 8 + (t4 << 1);
            const float b0v = bias[gn], b1v = bias[gn + 1];
            float2 o0 = make_float2(acc[mt][nt][0] + b0v, acc[mt][nt][1] + b1v);
            float2 o1 = make_float2(acc[mt][nt][2] + b0v, acc[mt][nt][3] + b1v);
            if (doRelu) {
                o0.x = fmaxf(o0.x, 0.f); o0.y = fmaxf(o0.y, 0.f);
                o1.x = fmaxf(o1.x, 0.f); o1.y = fmaxf(o1.y, 0.f);
            }
            *(float2*)(C + (size_t)gm * N + gn)       = o0;
            *(float2*)(C + (size_t)(gm + 8) * N + gn) = o1;
        }
    }
}

// ---------------- tiled attention ------------------------------------------------
// Block = (qtile of 32, h, b). 256 threads. Two-pass: scores in smem, softmax, PV.
__global__ __launch_bounds__(256) void attn_tile(
    const float* __restrict__ Q, const float* __restrict__ K,
    const float* __restrict__ V, float* __restrict__ O,
    int Sq, int Sk, int Skc, int causal)
{
    extern __shared__ float smf[];
    float* Qs = smf;                 // QT x 68
    float* Ks = Qs + QT * 68;        // 64 x 68 (K^T in phase1, V in phase3)
    float* sc = Ks + 64 * 68;        // QT x Skc

    const int tid = threadIdx.x;
    const int qtile = blockIdx.x, h = blockIdx.y, b = blockIdx.z;
    const int qbase = qtile * QT;
    const size_t hoff = (size_t)h * DHsz;

    const int tq = (tid >> 4) << 1;   // 0..30
    const int tk = (tid & 15) << 2;   // 0..60

    // init scores to -inf
    for (int i = tid; i < QT * Skc; i += 256) sc[i] = -1e30f;

    // load Q tile
    {
        const int qrow = tid >> 4;           // 0..15
        const int d4 = (tid & 15) << 2;
        #pragma unroll
        for (int p = 0; p < 2; p++) {
            const int qq = qrow + p * 16;
            const int qg = qbase + qq;
            float4 v4 = (qg < Sq)
                ? *(const float4*)(Q + (size_t)(b * Sq + qg) * Dsz + hoff + d4)
                : make_float4(0.f, 0.f, 0.f, 0.f);
            *(float4*)&Qs[qq * 68 + d4] = v4;
        }
    }
    __syncthreads();

    const int qend = qbase + QT - 1;

    // ---- phase 1: scores ----
    for (int c0 = 0; c0 < Sk; c0 += 64) {
        if (causal && c0 > qend) break;
        {
            const int kl = tid >> 4;
            const int d4 = (tid & 15) << 2;
            #pragma unroll
            for (int p = 0; p < 4; p++) {
                const int kk = kl + p * 16;
                const int kg = c0 + kk;
                float4 v4 = (kg < Sk)
                    ? *(const float4*)(K + (size_t)(b * Sk + kg) * Dsz + hoff + d4)
                    : make_float4(0.f, 0.f, 0.f, 0.f);
                Ks[(d4 + 0) * 68 + kk] = v4.x;
                Ks[(d4 + 1) * 68 + kk] = v4.y;
                Ks[(d4 + 2) * 68 + kk] = v4.z;
                Ks[(d4 + 3) * 68 + kk] = v4.w;
            }
        }
        __syncthreads();

        float a0[4] = {0.f, 0.f, 0.f, 0.f};
        float a1[4] = {0.f, 0.f, 0.f, 0.f};
        #pragma unroll 8
        for (int d = 0; d < 64; d++) {
            const float q0 = Qs[tq * 68 + d];
            const float q1 = Qs[(tq + 1) * 68 + d];
            const float4 k4 = *(const float4*)&Ks[d * 68 + tk];
            a0[0] = fmaf(q0, k4.x, a0[0]); a0[1] = fmaf(q0, k4.y, a0[1]);
            a0[2] = fmaf(q0, k4.z, a0[2]); a0[3] = fmaf(q0, k4.w, a0[3]);
            a1[0] = fmaf(q1, k4.x, a1[0]); a1[1] = fmaf(q1, k4.y, a1[1]);
            a1[2] = fmaf(q1, k4.z, a1[2]); a1[3] = fmaf(q1, k4.w, a1[3]);
        }
        #pragma unroll
        for (int j = 0; j < 4; j++) {
            const int kg = c0 + tk + j;
            if (kg < Sk) {
                if (!causal || kg <= qbase + tq)
                    sc[tq * Skc + kg] = a0[j] * 0.125f;
                if (!causal || kg <= qbase + tq + 1)
                    sc[(tq + 1) * Skc + kg] = a1[j] * 0.125f;
            }
        }
        __syncthreads();
    }
    __syncthreads();

    // ---- phase 2: softmax (warp per row) ----
    {
        const int lane = tid & 31, warp = tid >> 5;
        for (int r = warp; r < QT; r += 8) {
            float* row = sc + r * Skc;
            float m = -1e30f;
            for (int i = lane; i < Skc; i += 32) m = fmaxf(m, row[i]);
            m = warpMax(m);
            float s = 0.f;
            for (int i = lane; i < Skc; i += 32) {
                float e = __expf(row[i] - m);
                row[i] = e;
                s += e;
            }
            s = warpSum(s);
            const float inv = 1.f / s;
            for (int i = lane; i < Skc; i += 32) row[i] *= inv;
        }
    }
    __syncthreads();

    // ---- phase 3: P @ V ----
    float o0[4] = {0.f, 0.f, 0.f, 0.f};
    float o1[4] = {0.f, 0.f, 0.f, 0.f};
    for (int c0 = 0; c0 < Sk; c0 += 64) {
        if (causal && c0 > qend) break;
        {
            const int kl = tid >> 4;
            const int d4 = (tid & 15) << 2;
            #pragma unroll
            for (int p = 0; p < 4; p++) {
                const int kk = kl + p * 16;
                const int kg = c0 + kk;
                float4 v4 = (kg < Sk)
                    ? *(const float4*)(V + (size_t)(b * Sk + kg) * Dsz + hoff + d4)
                    : make_float4(0.f, 0.f, 0.f, 0.f);
                *(float4*)&Ks[kk * 68 + d4] = v4;
            }
        }
        __syncthreads();
        #pragma unroll 8
        for (int key = 0; key < 64; key++) {
            const float p0 = sc[tq * Skc + c0 + key];
            const float p1 = sc[(tq + 1) * Skc + c0 + key];
            const float4 v4 = *(const float4*)&Ks[key * 68 + tk];
            o0[0] = fmaf(p0, v4.x, o0[0]); o0[1] = fmaf(p0, v4.y, o0[1]);
            o0[2] = fmaf(p0, v4.z, o0[2]); o0[3] = fmaf(p0, v4.w, o0[3]);
            o1[0] = fmaf(p1, v4.x, o1[0]); o1[1] = fmaf(p1, v4.y, o1[1]);
            o1[2] = fmaf(p1, v4.z, o1[2]); o1[3] = fmaf(p1, v4.w, o1[3]);
        }
        __syncthreads();
    }
    // write O
    {
        const int qg0 = qbase + tq;
        if (qg0 < Sq)
            *(float4*)(O + (size_t)(b * Sq + qg0) * Dsz + hoff + tk) =
                make_float4(o0[0], o0[1], o0[2], o0[3]);
        const int qg1 = qg0 + 1;
        if (qg1 < Sq)
            *(float4*)(O + (size_t)(b * Sq + qg1) * Dsz + hoff + tk) =
                make_float4(o1[0], o1[1], o1[2], o1[3]);
    }
}

// ---------------- residual + LayerNorm -------------------------------------------
__global__ __launch_bounds__(128) void add_ln_kernel(
    float* __restrict__ h, const float* __restrict__ r,
    const float* __restrict__ scale, const float* __restrict__ bias)
{
    const int row = blockIdx.x;
    const int tid = threadIdx.x;
    const int lane = tid & 31, warp = tid >> 5;
    float* hp = h + (size_t)row * Dsz;
    const float* rp = r + (size_t)row * Dsz;

    float4 hv = *(const float4*)(hp + tid * 4);
    float4 rv = *(const float4*)(rp + tid * 4);
    float v0 = hv.x + rv.x, v1 = hv.y + rv.y, v2 = hv.z + rv.z, v3 = hv.w + rv.w;

    float sum = v0 + v1 + v2 + v3;
    float sq  = v0*v0 + v1*v1 + v2*v2 + v3*v3;
    sum = warpSum(sum); sq = warpSum(sq);

    __shared__ float s1[4], s2[4];
    if (lane == 0) { s1[warp] = sum; s2[warp] = sq; }
    __syncthreads();
    sum = s1[0] + s1[1] + s1[2] + s1[3];
    sq  = s2[0] + s2[1] + s2[2] + s2[3];

    const float mu = sum * (1.f / Dsz);
    const float var = sq * (1.f / Dsz) - mu * mu;
    const float rs = rsqrtf(var + 1e-5f);

    float4 sc4 = *(const float4*)(scale + tid * 4);
    float4 bi4 = *(const float4*)(bias + tid * 4);
    float4 o;
    o.x = (v0 - mu) * rs * sc4.x + bi4.x;
    o.y = (v1 - mu) * rs * sc4.y + bi4.y;
    o.z = (v2 - mu) * rs * sc4.z + bi4.z;
    o.w = (v3 - mu) * rs * sc4.w + bi4.w;
    *(float4*)(hp + tid * 4) = o;
}

// ---------------- embeddings ------------------------------------------------------
__device__ __forceinline__ float pos_enc(int pos, int d) {
    const int i2 = d & ~1;
    const float freq = expf(-(float)i2 * (9.210340371976184f / 512.f));
    const float ang = (float)pos * freq;
    return (d & 1) ? cosf(ang) : sinf(ang);
}

__global__ __launch_bounds__(512) void embed_src_kernel(
    const float* __restrict__ x, const float* __restrict__ w,
    const float* __restrict__ b, float* __restrict__ h)
{
    const int token = blockIdx.x;
    const int d = threadIdx.x;
    const int s = token % Ssz;
    const float x0 = x[token * 2 + 0], x1 = x[token * 2 + 1];
    h[(size_t)token * Dsz + d] = x0 * w[d] + x1 * w[Dsz + d] + b[d] + pos_enc(s, d);
}

__global__ __launch_bounds__(512) void embed_tgt_kernel(
    const float* __restrict__ y, const float* __restrict__ w,
    const float* __restrict__ b, float* __restrict__ dd)
{
    const int token = blockIdx.x;
    const int d = threadIdx.x;
    const int bb = token / Tsz, t = token % Tsz;
    const float val = (t == 0) ? 0.f : y[bb * Tsz + (t - 1)];
    dd[(size_t)token * Dsz + d] = val * w[d] + b[d] + pos_enc(t, d);
}

// ---------------- final projection -------------------------------------------------
__global__ __launch_bounds__(128) void out_proj_kernel(
    const float* __restrict__ dd, const float* __restrict__ w,
    const float* __restrict__ b, float* __restrict__ out)
{
    const int token = blockIdx.x;
    const int tid = threadIdx.x;
    const int lane = tid & 31, warp = tid >> 5;
    float s = 0.f;
    for (int i = tid; i < Dsz; i += 128)
        s += dd[(size_t)token * Dsz + i] * w[i];
    s = warpSum(s);
    __shared__ float smr[4];
    if (lane == 0) smr[warp] = s;
    __syncthreads();
    if (tid == 0) out[token] = smr[0] + smr[1] + smr[2] + smr[3] + b[0];
}

// ---------------- host orchestration ----------------------------------------------
extern "C" void kernel_launch(void* const* d_in, const int* in_sizes, int n_in,
                              void* d_out, int out_size)
{
    const float* x          = (const float*)d_in[0];
    const float* y          = (const float*)d_in[1];
    const float* src_w      = (const float*)d_in[2];
    const float* src_b      = (const float*)d_in[3];
    const float* tgt_w      = (const float*)d_in[4];
    const float* tgt_b      = (const float*)d_in[5];
    const float* enc_attn_w = (const float*)d_in[6];
    const float* enc_attn_b = (const float*)d_in[7];
    const float* enc_ffn_w1 = (const float*)d_in[8];
    const float* enc_ffn_b1 = (const float*)d_in[9];
    const float* enc_ffn_w2 = (const float*)d_in[10];
    const float* enc_ffn_b2 = (const float*)d_in[11];
    const float* enc_ln_s   = (const float*)d_in[12];
    const float* enc_ln_b   = (const float*)d_in[13];
    const float* dec_self_w = (const float*)d_in[14];
    const float* dec_self_b = (const float*)d_in[15];
    const float* dec_cross_w= (const float*)d_in[16];
    const float* dec_cross_b= (const float*)d_in[17];
    const float* dec_ffn_w1 = (const float*)d_in[18];
    const float* dec_ffn_b1 = (const float*)d_in[19];
    const float* dec_ffn_w2 = (const float*)d_in[20];
    const float* dec_ffn_b2 = (const float*)d_in[21];
    const float* dec_ln_s   = (const float*)d_in[22];
    const float* dec_ln_b   = (const float*)d_in[23];
    const float* out_w      = (const float*)d_in[24];
    const float* out_b      = (const float*)d_in[25];

    float *h, *tmp, *q, *k, *v, *ffn, *dd, *dq, *dtmp;
    cudaGetSymbolAddress((void**)&h,    g_h);
    cudaGetSymbolAddress((void**)&tmp,  g_tmp);
    cudaGetSymbolAddress((void**)&q,    g_q);
    cudaGetSymbolAddress((void**)&k,    g_k);
    cudaGetSymbolAddress((void**)&v,    g_v);
    cudaGetSymbolAddress((void**)&ffn,  g_ffn);
    cudaGetSymbolAddress((void**)&dd,   g_d);
    cudaGetSymbolAddress((void**)&dq,   g_dq);
    cudaGetSymbolAddress((void**)&dtmp, g_dtmp);

    const int Me = Bsz * Ssz;   // 16384
    const int Md = Bsz * Tsz;   // 5760
    const size_t DD = (size_t)Dsz * Dsz;

    // attention smem sizes
    const int SkcE = 512;  // encoder/cross key span (padded to 64)
    const int SkcD = 192;  // decoder self
    const int smemE = (QT * 68 + 64 * 68 + QT * SkcE) * 4;
    const int smemD = (QT * 68 + 64 * 68 + QT * SkcD) * 4;
    cudaFuncSetAttribute(attn_tile, cudaFuncAttributeMaxDynamicSharedMemorySize, smemE);

    const int qtE = Ssz / QT;                 // 16
    const int qtD = (Tsz + QT - 1) / QT;      // 6

    dim3 blk(256);
    dim3 gE_D(Dsz / 128, Me / 128);
    dim3 gE_F(Fsz / 128, Me / 128);
    dim3 gD_D(Dsz / 128, Md / 128);
    dim3 gD_F(Fsz / 128, Md / 128);

    // ===== encoder =====
    embed_src_kernel<<<Me, 512>>>(x, src_w, src_b, h);
    for (int l = 0; l < Lsz; l++) {
        const float* w  = enc_attn_w + (size_t)l * 4 * DD;
        const float* wb = enc_attn_b + (size_t)l * 4 * Dsz;
        gemm_tf32<<<gE_D, blk>>>(h, w,          wb,          q, Me, Dsz, Dsz, 0);
        gemm_tf32<<<gE_D, blk>>>(h, w + DD,     wb + Dsz,    k, Me, Dsz, Dsz, 0);
        gemm_tf32<<<gE_D, blk>>>(h, w + 2*DD,   wb + 2*Dsz,  v, Me, Dsz, Dsz, 0);
        attn_tile<<<dim3(qtE, Hsz, Bsz), 256, smemE>>>(q, k, v, tmp, Ssz, Ssz, SkcE, 0);
        gemm_tf32<<<gE_D, blk>>>(tmp, w + 3*DD, wb + 3*Dsz,  q, Me, Dsz, Dsz, 0);
        add_ln_kernel<<<Me, 128>>>(h, q, enc_ln_s + (size_t)(l*2)*Dsz,
                                         enc_ln_b + (size_t)(l*2)*Dsz);
        gemm_tf32<<<gE_F, blk>>>(h, enc_ffn_w1 + (size_t)l*Dsz*Fsz,
                                 enc_ffn_b1 + (size_t)l*Fsz, ffn, Me, Fsz, Dsz, 1);
        gemm_tf32<<<gE_D, blk>>>(ffn, enc_ffn_w2 + (size_t)l*Fsz*Dsz,
                                 enc_ffn_b2 + (size_t)l*Dsz, tmp, Me, Dsz, Fsz, 0);
        add_ln_kernel<<<Me, 128>>>(h, tmp, enc_ln_s + (size_t)(l*2+1)*Dsz,
                                           enc_ln_b + (size_t)(l*2+1)*Dsz);
    }

    // ===== decoder =====
    embed_tgt_kernel<<<Md, 512>>>(y, tgt_w, tgt_b, dd);
    for (int l = 0; l < Lsz; l++) {
        const float* w  = dec_self_w + (size_t)l * 4 * DD;
        const float* wb = dec_self_b + (size_t)l * 4 * Dsz;
        gemm_tf32<<<gD_D, blk>>>(dd, w,        wb,         dq, Md, Dsz, Dsz, 0);
        gemm_tf32<<<gD_D, blk>>>(dd, w + DD,   wb + Dsz,   k,  Md, Dsz, Dsz, 0);
        gemm_tf32<<<gD_D, blk>>>(dd, w + 2*DD, wb + 2*Dsz, v,  Md, Dsz, Dsz, 0);
        attn_tile<<<dim3(qtD, Hsz, Bsz), 256, smemD>>>(dq, k, v, dtmp, Tsz, Tsz, SkcD, 1);
        gemm_tf32<<<gD_D, blk>>>(dtmp, w + 3*DD, wb + 3*Dsz, dq, Md, Dsz, Dsz, 0);
        add_ln_kernel<<<Md, 128>>>(dd, dq, dec_ln_s + (size_t)(l*3)*Dsz,
                                           dec_ln_b + (size_t)(l*3)*Dsz);

        const float* cw  = dec_cross_w + (size_t)l * 4 * DD;
        const float* cwb = dec_cross_b + (size_t)l * 4 * Dsz;
        gemm_tf32<<<gD_D, blk>>>(dd, cw,        cwb,         dq, Md, Dsz, Dsz, 0);
        gemm_tf32<<<gE_D, blk>>>(h,  cw + DD,   cwb + Dsz,   k,  Me, Dsz, Dsz, 0);
        gemm_tf32<<<gE_D, blk>>>(h,  cw + 2*DD, cwb + 2*Dsz, v,  Me, Dsz, Dsz, 0);
        attn_tile<<<dim3(qtD, Hsz, Bsz), 256, smemE>>>(dq, k, v, dtmp, Tsz, Ssz, SkcE, 0);
        gemm_tf32<<<gD_D, blk>>>(dtmp, cw + 3*DD, cwb + 3*Dsz, dq, Md, Dsz, Dsz, 0);
        add_ln_kernel<<<Md, 128>>>(dd, dq, dec_ln_s + (size_t)(l*3+1)*Dsz,
                                           dec_ln_b + (size_t)(l*3+1)*Dsz);

        gemm_tf32<<<gD_F, blk>>>(dd, dec_ffn_w1 + (size_t)l*Dsz*Fsz,
                                 dec_ffn_b1 + (size_t)l*Fsz, ffn, Md, Fsz, Dsz, 1);
        gemm_tf32<<<gD_D, blk>>>(ffn, dec_ffn_w2 + (size_t)l*Fsz*Dsz,
                                 dec_ffn_b2 + (size_t)l*Dsz, dtmp, Md, Dsz, Fsz, 0);
        add_ln_kernel<<<Md, 128>>>(dd, dtmp, dec_ln_s + (size_t)(l*3+2)*Dsz,
                                             dec_ln_b + (size_t)(l*3+2)*Dsz);
    }

    out_proj_kernel<<<Md, 128>>>(dd, out_w, out_b, (float*)d_out);
}

// round 4
// speedup vs baseline: 7.3965x; 1.4910x over previous
#include <cuda_runtime.h>
#include <math.h>
#include <stdint.h>

#define Bsz 32
#define Ssz 512
#define Tsz 180
#define Dsz 512
#define Fsz 2048
#define Lsz 6
#define Hsz 8
#define DHsz 64

__device__ float g_h   [Bsz*Ssz*Dsz];
__device__ float g_tmp [Bsz*Ssz*Dsz];
__device__ float g_q   [Bsz*Ssz*Dsz];
__device__ float g_k   [Bsz*Ssz*Dsz];
__device__ float g_v   [Bsz*Ssz*Dsz];
__device__ float g_ffn [Bsz*Ssz*Fsz];
__device__ float g_d   [Bsz*Tsz*Dsz];
__device__ float g_dq  [Bsz*Tsz*Dsz];
__device__ float g_dtmp[Bsz*Tsz*Dsz];

__device__ __forceinline__ float warpSum(float v) {
    #pragma unroll
    for (int o = 16; o; o >>= 1) v += __shfl_xor_sync(0xffffffffu, v, o);
    return v;
}
__device__ __forceinline__ float warpMax(float v) {
    #pragma unroll
    for (int o = 16; o; o >>= 1) v = fmaxf(v, __shfl_xor_sync(0xffffffffu, v, o));
    return v;
}
__device__ __forceinline__ uint4 cvt_tf32x4(float4 v) {
    uint4 u;
    asm("cvt.rna.tf32.f32 %0, %1;" : "=r"(u.x) : "f"(v.x));
    asm("cvt.rna.tf32.f32 %0, %1;" : "=r"(u.y) : "f"(v.y));
    asm("cvt.rna.tf32.f32 %0, %1;" : "=r"(u.z) : "f"(v.z));
    asm("cvt.rna.tf32.f32 %0, %1;" : "=r"(u.w) : "f"(v.w));
    return u;
}
__device__ __forceinline__ float cvt_tf32(float v) {
    uint32_t u;
    asm("cvt.rna.tf32.f32 %0, %1;" : "=r"(u) : "f"(v));
    return __uint_as_float(u);
}
#define MMA_TF32(c, a, b) \
    asm volatile("mma.sync.aligned.m16n8k8.row.col.f32.tf32.tf32.f32 " \
        "{%0,%1,%2,%3}, {%4,%5,%6,%7}, {%8,%9}, {%0,%1,%2,%3};" \
        : "+f"((c)[0]), "+f"((c)[1]), "+f"((c)[2]), "+f"((c)[3]) \
        : "r"((a)[0]), "r"((a)[1]), "r"((a)[2]), "r"((a)[3]), \
          "r"((b)[0]), "r"((b)[1]))

// ---------------- TF32 GEMM (unchanged, proven) -----------------------------------
__global__ __launch_bounds__(256, 2) void gemm_tf32(
    const float* __restrict__ A, const float* __restrict__ B,
    const float* __restrict__ bias, float* __restrict__ C,
    int M, int N, int K, int doRelu)
{
    __shared__ uint32_t As[2][128 * 20];
    __shared__ uint32_t Bs[2][16 * 136];
    const int tid  = threadIdx.x;
    const int lane = tid & 31, warp = tid >> 5;
    const int g = lane >> 2, t4 = lane & 3;
    const int wm = (warp >> 2) << 6, wn = (warp & 3) << 5;
    const int bm = blockIdx.y << 7, bn = blockIdx.x << 7;
    const int ar = tid >> 2, ac = (tid & 3) << 2;
    const int br = tid >> 5, bc = lane << 2;

    const float* Ap0 = A + (size_t)(bm + ar) * K + ac;
    const float* Ap1 = A + (size_t)(bm + ar + 64) * K + ac;
    const float* Bp0 = B + (size_t)br * N + bn + bc;
    const float* Bp1 = B + (size_t)(br + 8) * N + bn + bc;

    float acc[4][4][4] = {};
    float4 ra0 = *(const float4*)Ap0, ra1 = *(const float4*)Ap1;
    float4 rb0 = *(const float4*)Bp0, rb1 = *(const float4*)Bp1;
    *(uint4*)&As[0][ar * 20 + ac]        = cvt_tf32x4(ra0);
    *(uint4*)&As[0][(ar + 64) * 20 + ac] = cvt_tf32x4(ra1);
    *(uint4*)&Bs[0][br * 136 + bc]       = cvt_tf32x4(rb0);
    *(uint4*)&Bs[0][(br + 8) * 136 + bc] = cvt_tf32x4(rb1);
    __syncthreads();

    int buf = 0;
    for (int k0 = 16; k0 < K; k0 += 16) {
        ra0 = *(const float4*)(Ap0 + k0);
        ra1 = *(const float4*)(Ap1 + k0);
        rb0 = *(const float4*)(Bp0 + (size_t)k0 * N);
        rb1 = *(const float4*)(Bp1 + (size_t)k0 * N);
        #pragma unroll
        for (int kk = 0; kk < 2; kk++) {
            uint32_t af[4][4], bf[4][2];
            #pragma unroll
            for (int mt = 0; mt < 4; mt++) {
                int base = (wm + mt * 16 + g) * 20 + kk * 8 + t4;
                af[mt][0] = As[buf][base];       af[mt][1] = As[buf][base + 160];
                af[mt][2] = As[buf][base + 4];   af[mt][3] = As[buf][base + 164];
            }
            #pragma unroll
            for (int nt = 0; nt < 4; nt++) {
                int base = (kk * 8 + t4) * 136 + wn + nt * 8 + g;
                bf[nt][0] = Bs[buf][base];  bf[nt][1] = Bs[buf][base + 544];
            }
            #pragma unroll
            for (int mt = 0; mt < 4; mt++)
                #pragma unroll
                for (int nt = 0; nt < 4; nt++)
                    MMA_TF32(acc[mt][nt], af[mt], bf[nt]);
        }
        const int nb = buf ^ 1;
        *(uint4*)&As[nb][ar * 20 + ac]        = cvt_tf32x4(ra0);
        *(uint4*)&As[nb][(ar + 64) * 20 + ac] = cvt_tf32x4(ra1);
        *(uint4*)&Bs[nb][br * 136 + bc]       = cvt_tf32x4(rb0);
        *(uint4*)&Bs[nb][(br + 8) * 136 + bc] = cvt_tf32x4(rb1);
        __syncthreads();
        buf = nb;
    }
    #pragma unroll
    for (int kk = 0; kk < 2; kk++) {
        uint32_t af[4][4], bf[4][2];
        #pragma unroll
        for (int mt = 0; mt < 4; mt++) {
            int base = (wm + mt * 16 + g) * 20 + kk * 8 + t4;
            af[mt][0] = As[buf][base];       af[mt][1] = As[buf][base + 160];
            af[mt][2] = As[buf][base + 4];   af[mt][3] = As[buf][base + 164];
        }
        #pragma unroll
        for (int nt = 0; nt < 4; nt++) {
            int base = (kk * 8 + t4) * 136 + wn + nt * 8 + g;
            bf[nt][0] = Bs[buf][base];  bf[nt][1] = Bs[buf][base + 544];
        }
        #pragma unroll
        for (int mt = 0; mt < 4; mt++)
            #pragma unroll
            for (int nt = 0; nt < 4; nt++)
                MMA_TF32(acc[mt][nt], af[mt], bf[nt]);
    }
    #pragma unroll
    for (int mt = 0; mt < 4; mt++) {
        const int gm = bm + wm + mt * 16 + g;
        #pragma unroll
        for (int nt = 0; nt < 4; nt++) {
            const int gn = bn + wn + nt * 8 + (t4 << 1);
            const float b0v = bias[gn], b1v = bias[gn + 1];
            float2 o0 = make_float2(acc[mt][nt][0] + b0v, acc[mt][nt][1] + b1v);
            float2 o1 = make_float2(acc[mt][nt][2] + b0v, acc[mt][nt][3] + b1v);
            if (doRelu) {
                o0.x = fmaxf(o0.x, 0.f); o0.y = fmaxf(o0.y, 0.f);
                o1.x = fmaxf(o1.x, 0.f); o1.y = fmaxf(o1.y, 0.f);
            }
            *(float2*)(C + (size_t)gm * N + gn)       = o0;
            *(float2*)(C + (size_t)(gm + 8) * N + gn) = o1;
        }
    }
}

// ---------------- tensor-core flash attention --------------------------------------
// Block: 64 q-rows per (h,b). 256 thr / 8 warps: wm=w&3 (q slice 16), wn=w>>2
// (key/d half 32). Online softmax over 64-key chunks. Q frags persistent.
#define ATT_SMEM ((4 * 64 * 68 + 192) * 4)

__global__ __launch_bounds__(256) void attn_mma(
    const float* __restrict__ Q, const float* __restrict__ K,
    const float* __restrict__ V, float* __restrict__ O,
    int Sq, int Sk, int causal)
{
    extern __shared__ float sm[];
    float* Qs = sm;            // 64 x 68
    float* Ks = sm + 4352;     // 64 x 68
    float* Vs = sm + 8704;     // 64 x 68
    float* Ss = sm + 13056;    // 64 x 68
    float* m_row = sm + 17408; // 64
    float* s_row = m_row + 64; // 64
    float* f_row = s_row + 64; // 64

    const int tid = threadIdx.x, lane = tid & 31, w = tid >> 5;
    const int wm = w & 3, wn = w >> 2;
    const int g = lane >> 2, t4 = lane & 3;
    const int qbase = blockIdx.x * 64;
    const int h = blockIdx.y, b = blockIdx.z;
    const size_t hoff = (size_t)h * DHsz;

    // stage Q (tf32)
    #pragma unroll
    for (int p = 0; p < 4; p++) {
        const int row = (tid >> 4) + p * 16;
        const int d4  = (tid & 15) << 2;
        const int qg  = qbase + row;
        float4 v4 = (qg < Sq)
            ? *(const float4*)(Q + (size_t)(b * Sq + qg) * Dsz + hoff + d4)
            : make_float4(0.f, 0.f, 0.f, 0.f);
        *(uint4*)&Qs[row * 68 + d4] = cvt_tf32x4(v4);
    }
    if (tid < 64) { m_row[tid] = -1e30f; s_row[tid] = 0.f; }
    __syncthreads();

    // persistent Q fragments
    const int qr = wm * 16 + g;
    uint32_t qf[8][4];
    #pragma unroll
    for (int kk = 0; kk < 8; kk++) {
        qf[kk][0] = __float_as_uint(Qs[qr * 68 + kk * 8 + t4]);
        qf[kk][1] = __float_as_uint(Qs[(qr + 8) * 68 + kk * 8 + t4]);
        qf[kk][2] = __float_as_uint(Qs[qr * 68 + kk * 8 + t4 + 4]);
        qf[kk][3] = __float_as_uint(Qs[(qr + 8) * 68 + kk * 8 + t4 + 4]);
    }

    float acc_o[4][4] = {};
    const int qend = qbase + 63;

    for (int c0 = 0; c0 < Sk; c0 += 64) {
        if (causal && c0 > qend) break;

        // stage K, V (tf32)
        #pragma unroll
        for (int p = 0; p < 4; p++) {
            const int row = (tid >> 4) + p * 16;
            const int d4  = (tid & 15) << 2;
            const int kg  = c0 + row;
            float4 kv = make_float4(0.f,0.f,0.f,0.f), vv = kv;
            if (kg < Sk) {
                kv = *(const float4*)(K + (size_t)(b * Sk + kg) * Dsz + hoff + d4);
                vv = *(const float4*)(V + (size_t)(b * Sk + kg) * Dsz + hoff + d4);
            }
            *(uint4*)&Ks[row * 68 + d4] = cvt_tf32x4(kv);
            *(uint4*)&Vs[row * 68 + d4] = cvt_tf32x4(vv);
        }
        __syncthreads();

        // S = Q @ K^T : per warp 16x32
        float acc_s[4][4] = {};
        #pragma unroll
        for (int kk = 0; kk < 8; kk++) {
            #pragma unroll
            for (int nt = 0; nt < 4; nt++) {
                const int key = wn * 32 + nt * 8 + g;
                uint32_t bf[2];
                bf[0] = __float_as_uint(Ks[key * 68 + kk * 8 + t4]);
                bf[1] = __float_as_uint(Ks[key * 68 + kk * 8 + t4 + 4]);
                MMA_TF32(acc_s[nt], qf[kk], bf);
            }
        }
        // scale + mask + store scores
        {
            const int qg0 = qbase + qr, qg1 = qg0 + 8;
            #pragma unroll
            for (int nt = 0; nt < 4; nt++) {
                const int cl = wn * 32 + nt * 8 + (t4 << 1);
                const int kg = c0 + cl;
                float s00 = acc_s[nt][0] * 0.125f, s01 = acc_s[nt][1] * 0.125f;
                float s10 = acc_s[nt][2] * 0.125f, s11 = acc_s[nt][3] * 0.125f;
                if (kg >= Sk || (causal && kg > qg0)) s00 = -1e30f;
                if (kg+1 >= Sk || (causal && kg+1 > qg0)) s01 = -1e30f;
                if (kg >= Sk || (causal && kg > qg1)) s10 = -1e30f;
                if (kg+1 >= Sk || (causal && kg+1 > qg1)) s11 = -1e30f;
                Ss[qr * 68 + cl] = s00;      Ss[qr * 68 + cl + 1] = s01;
                Ss[(qr+8) * 68 + cl] = s10;  Ss[(qr+8) * 68 + cl + 1] = s11;
            }
        }
        __syncthreads();

        // online softmax: warp w owns rows w*8 .. w*8+7
        #pragma unroll
        for (int rr = 0; rr < 8; rr++) {
            const int r = w * 8 + rr;
            float s0v = Ss[r * 68 + lane];
            float s1v = Ss[r * 68 + lane + 32];
            const float mx = warpMax(fmaxf(s0v, s1v));
            const float mold = m_row[r];
            const float mnew = fmaxf(mold, mx);
            float p0 = __expf(s0v - mnew);
            float p1 = __expf(s1v - mnew);
            const float sum = warpSum(p0 + p1);
            Ss[r * 68 + lane]      = cvt_tf32(p0);
            Ss[r * 68 + lane + 32] = cvt_tf32(p1);
            if (lane == 0) {
                const float f = __expf(mold - mnew);
                f_row[r] = f;
                s_row[r] = s_row[r] * f + sum;
                m_row[r] = mnew;
            }
        }
        __syncthreads();

        // rescale O, then O += P @ V
        {
            const float f0 = f_row[qr], f1 = f_row[qr + 8];
            #pragma unroll
            for (int nt = 0; nt < 4; nt++) {
                acc_o[nt][0] *= f0; acc_o[nt][1] *= f0;
                acc_o[nt][2] *= f1; acc_o[nt][3] *= f1;
            }
        }
        #pragma unroll
        for (int kk = 0; kk < 8; kk++) {
            uint32_t af[4];
            af[0] = __float_as_uint(Ss[qr * 68 + kk * 8 + t4]);
            af[1] = __float_as_uint(Ss[(qr + 8) * 68 + kk * 8 + t4]);
            af[2] = __float_as_uint(Ss[qr * 68 + kk * 8 + t4 + 4]);
            af[3] = __float_as_uint(Ss[(qr + 8) * 68 + kk * 8 + t4 + 4]);
            #pragma unroll
            for (int nt = 0; nt < 4; nt++) {
                const int dcol = wn * 32 + nt * 8 + g;
                uint32_t bf[2];
                bf[0] = __float_as_uint(Vs[(kk * 8 + t4) * 68 + dcol]);
                bf[1] = __float_as_uint(Vs[(kk * 8 + t4 + 4) * 68 + dcol]);
                MMA_TF32(acc_o[nt], af, bf);
            }
        }
        __syncthreads();
    }

    // normalize + write O
    const float inv0 = 1.f / s_row[qr];
    const float inv1 = 1.f / s_row[qr + 8];
    const int qg0 = qbase + qr, qg1 = qg0 + 8;
    #pragma unroll
    for (int nt = 0; nt < 4; nt++) {
        const int dcol = wn * 32 + nt * 8 + (t4 << 1);
        if (qg0 < Sq)
            *(float2*)(O + (size_t)(b * Sq + qg0) * Dsz + hoff + dcol) =
                make_float2(acc_o[nt][0] * inv0, acc_o[nt][1] * inv0);
        if (qg1 < Sq)
            *(float2*)(O + (size_t)(b * Sq + qg1) * Dsz + hoff + dcol) =
                make_float2(acc_o[nt][2] * inv1, acc_o[nt][3] * inv1);
    }
}

// ---------------- residual + LayerNorm ---------------------------------------------
__global__ __launch_bounds__(128) void add_ln_kernel(
    float* __restrict__ h, const float* __restrict__ r,
    const float* __restrict__ scale, const float* __restrict__ bias)
{
    const int row = blockIdx.x;
    const int tid = threadIdx.x;
    const int lane = tid & 31, warp = tid >> 5;
    float* hp = h + (size_t)row * Dsz;
    const float* rp = r + (size_t)row * Dsz;

    float4 hv = *(const float4*)(hp + tid * 4);
    float4 rv = *(const float4*)(rp + tid * 4);
    float v0 = hv.x + rv.x, v1 = hv.y + rv.y, v2 = hv.z + rv.z, v3 = hv.w + rv.w;

    float sum = v0 + v1 + v2 + v3;
    float sq  = v0*v0 + v1*v1 + v2*v2 + v3*v3;
    sum = warpSum(sum); sq = warpSum(sq);

    __shared__ float s1[4], s2[4];
    if (lane == 0) { s1[warp] = sum; s2[warp] = sq; }
    __syncthreads();
    sum = s1[0] + s1[1] + s1[2] + s1[3];
    sq  = s2[0] + s2[1] + s2[2] + s2[3];

    const float mu = sum * (1.f / Dsz);
    const float var = sq * (1.f / Dsz) - mu * mu;
    const float rs = rsqrtf(var + 1e-5f);

    float4 sc4 = *(const float4*)(scale + tid * 4);
    float4 bi4 = *(const float4*)(bias + tid * 4);
    float4 o;
    o.x = (v0 - mu) * rs * sc4.x + bi4.x;
    o.y = (v1 - mu) * rs * sc4.y + bi4.y;
    o.z = (v2 - mu) * rs * sc4.z + bi4.z;
    o.w = (v3 - mu) * rs * sc4.w + bi4.w;
    *(float4*)(hp + tid * 4) = o;
}

// ---------------- embeddings --------------------------------------------------------
__device__ __forceinline__ float pos_enc(int pos, int d) {
    const int i2 = d & ~1;
    const float freq = expf(-(float)i2 * (9.210340371976184f / 512.f));
    const float ang = (float)pos * freq;
    return (d & 1) ? cosf(ang) : sinf(ang);
}
__global__ __launch_bounds__(512) void embed_src_kernel(
    const float* __restrict__ x, const float* __restrict__ w,
    const float* __restrict__ b, float* __restrict__ h)
{
    const int token = blockIdx.x;
    const int d = threadIdx.x;
    const int s = token % Ssz;
    const float x0 = x[token * 2 + 0], x1 = x[token * 2 + 1];
    h[(size_t)token * Dsz + d] = x0 * w[d] + x1 * w[Dsz + d] + b[d] + pos_enc(s, d);
}
__global__ __launch_bounds__(512) void embed_tgt_kernel(
    const float* __restrict__ y, const float* __restrict__ w,
    const float* __restrict__ b, float* __restrict__ dd)
{
    const int token = blockIdx.x;
    const int d = threadIdx.x;
    const int bb = token / Tsz, t = token % Tsz;
    const float val = (t == 0) ? 0.f : y[bb * Tsz + (t - 1)];
    dd[(size_t)token * Dsz + d] = val * w[d] + b[d] + pos_enc(t, d);
}

// ---------------- final projection ---------------------------------------------------
__global__ __launch_bounds__(128) void out_proj_kernel(
    const float* __restrict__ dd, const float* __restrict__ w,
    const float* __restrict__ b, float* __restrict__ out)
{
    const int token = blockIdx.x;
    const int tid = threadIdx.x;
    const int lane = tid & 31, warp = tid >> 5;
    float s = 0.f;
    for (int i = tid; i < Dsz; i += 128)
        s += dd[(size_t)token * Dsz + i] * w[i];
    s = warpSum(s);
    __shared__ float smr[4];
    if (lane == 0) smr[warp] = s;
    __syncthreads();
    if (tid == 0) out[token] = smr[0] + smr[1] + smr[2] + smr[3] + b[0];
}

// ---------------- host orchestration -------------------------------------------------
extern "C" void kernel_launch(void* const* d_in, const int* in_sizes, int n_in,
                              void* d_out, int out_size)
{
    const float* x          = (const float*)d_in[0];
    const float* y          = (const float*)d_in[1];
    const float* src_w      = (const float*)d_in[2];
    const float* src_b      = (const float*)d_in[3];
    const float* tgt_w      = (const float*)d_in[4];
    const float* tgt_b      = (const float*)d_in[5];
    const float* enc_attn_w = (const float*)d_in[6];
    const float* enc_attn_b = (const float*)d_in[7];
    const float* enc_ffn_w1 = (const float*)d_in[8];
    const float* enc_ffn_b1 = (const float*)d_in[9];
    const float* enc_ffn_w2 = (const float*)d_in[10];
    const float* enc_ffn_b2 = (const float*)d_in[11];
    const float* enc_ln_s   = (const float*)d_in[12];
    const float* enc_ln_b   = (const float*)d_in[13];
    const float* dec_self_w = (const float*)d_in[14];
    const float* dec_self_b = (const float*)d_in[15];
    const float* dec_cross_w= (const float*)d_in[16];
    const float* dec_cross_b= (const float*)d_in[17];
    const float* dec_ffn_w1 = (const float*)d_in[18];
    const float* dec_ffn_b1 = (const float*)d_in[19];
    const float* dec_ffn_w2 = (const float*)d_in[20];
    const float* dec_ffn_b2 = (const float*)d_in[21];
    const float* dec_ln_s   = (const float*)d_in[22];
    const float* dec_ln_b   = (const float*)d_in[23];
    const float* out_w      = (const float*)d_in[24];
    const float* out_b      = (const float*)d_in[25];

    float *h, *tmp, *q, *k, *v, *ffn, *dd, *dq, *dtmp;
    cudaGetSymbolAddress((void**)&h,    g_h);
    cudaGetSymbolAddress((void**)&tmp,  g_tmp);
    cudaGetSymbolAddress((void**)&q,    g_q);
    cudaGetSymbolAddress((void**)&k,    g_k);
    cudaGetSymbolAddress((void**)&v,    g_v);
    cudaGetSymbolAddress((void**)&ffn,  g_ffn);
    cudaGetSymbolAddress((void**)&dd,   g_d);
    cudaGetSymbolAddress((void**)&dq,   g_dq);
    cudaGetSymbolAddress((void**)&dtmp, g_dtmp);

    const int Me = Bsz * Ssz;   // 16384
    const int Md = Bsz * Tsz;   // 5760
    const size_t DD = (size_t)Dsz * Dsz;

    cudaFuncSetAttribute(attn_mma, cudaFuncAttributeMaxDynamicSharedMemorySize, ATT_SMEM);
    const int qtE = Ssz / 64;                 // 8
    const int qtD = (Tsz + 63) / 64;          // 3

    dim3 blk(256);
    dim3 gE_D(Dsz / 128, Me / 128);
    dim3 gE_F(Fsz / 128, Me / 128);
    dim3 gD_D(Dsz / 128, Md / 128);
    dim3 gD_F(Fsz / 128, Md / 128);

    // ===== encoder =====
    embed_src_kernel<<<Me, 512>>>(x, src_w, src_b, h);
    for (int l = 0; l < Lsz; l++) {
        const float* w  = enc_attn_w + (size_t)l * 4 * DD;
        const float* wb = enc_attn_b + (size_t)l * 4 * Dsz;
        gemm_tf32<<<gE_D, blk>>>(h, w,          wb,          q, Me, Dsz, Dsz, 0);
        gemm_tf32<<<gE_D, blk>>>(h, w + DD,     wb + Dsz,    k, Me, Dsz, Dsz, 0);
        gemm_tf32<<<gE_D, blk>>>(h, w + 2*DD,   wb + 2*Dsz,  v, Me, Dsz, Dsz, 0);
        attn_mma<<<dim3(qtE, Hsz, Bsz), 256, ATT_SMEM>>>(q, k, v, tmp, Ssz, Ssz, 0);
        gemm_tf32<<<gE_D, blk>>>(tmp, w + 3*DD, wb + 3*Dsz,  q, Me, Dsz, Dsz, 0);
        add_ln_kernel<<<Me, 128>>>(h, q, enc_ln_s + (size_t)(l*2)*Dsz,
                                         enc_ln_b + (size_t)(l*2)*Dsz);
        gemm_tf32<<<gE_F, blk>>>(h, enc_ffn_w1 + (size_t)l*Dsz*Fsz,
                                 enc_ffn_b1 + (size_t)l*Fsz, ffn, Me, Fsz, Dsz, 1);
        gemm_tf32<<<gE_D, blk>>>(ffn, enc_ffn_w2 + (size_t)l*Fsz*Dsz,
                                 enc_ffn_b2 + (size_t)l*Dsz, tmp, Me, Dsz, Fsz, 0);
        add_ln_kernel<<<Me, 128>>>(h, tmp, enc_ln_s + (size_t)(l*2+1)*Dsz,
                                           enc_ln_b + (size_t)(l*2+1)*Dsz);
    }

    // ===== decoder =====
    embed_tgt_kernel<<<Md, 512>>>(y, tgt_w, tgt_b, dd);
    for (int l = 0; l < Lsz; l++) {
        const float* w  = dec_self_w + (size_t)l * 4 * DD;
        const float* wb = dec_self_b + (size_t)l * 4 * Dsz;
        gemm_tf32<<<gD_D, blk>>>(dd, w,        wb,         dq, Md, Dsz, Dsz, 0);
        gemm_tf32<<<gD_D, blk>>>(dd, w + DD,   wb + Dsz,   k,  Md, Dsz, Dsz, 0);
        gemm_tf32<<<gD_D, blk>>>(dd, w + 2*DD, wb + 2*Dsz, v,  Md, Dsz, Dsz, 0);
        attn_mma<<<dim3(qtD, Hsz, Bsz), 256, ATT_SMEM>>>(dq, k, v, dtmp, Tsz, Tsz, 1);
        gemm_tf32<<<gD_D, blk>>>(dtmp, w + 3*DD, wb + 3*Dsz, dq, Md, Dsz, Dsz, 0);
        add_ln_kernel<<<Md, 128>>>(dd, dq, dec_ln_s + (size_t)(l*3)*Dsz,
                                           dec_ln_b + (size_t)(l*3)*Dsz);

        const float* cw  = dec_cross_w + (size_t)l * 4 * DD;
        const float* cwb = dec_cross_b + (size_t)l * 4 * Dsz;
        gemm_tf32<<<gD_D, blk>>>(dd, cw,        cwb,         dq, Md, Dsz, Dsz, 0);
        gemm_tf32<<<gE_D, blk>>>(h,  cw + DD,   cwb + Dsz,   k,  Me, Dsz, Dsz, 0);
        gemm_tf32<<<gE_D, blk>>>(h,  cw + 2*DD, cwb + 2*Dsz, v,  Me, Dsz, Dsz, 0);
        attn_mma<<<dim3(qtD, Hsz, Bsz), 256, ATT_SMEM>>>(dq, k, v, dtmp, Tsz, Ssz, 0);
        gemm_tf32<<<gD_D, blk>>>(dtmp, cw + 3*DD, cwb + 3*Dsz, dq, Md, Dsz, Dsz, 0);
        add_ln_kernel<<<Md, 128>>>(dd, dq, dec_ln_s + (size_t)(l*3+1)*Dsz,
                                           dec_ln_b + (size_t)(l*3+1)*Dsz);

        gemm_tf32<<<gD_F, blk>>>(dd, dec_ffn_w1 + (size_t)l*Dsz*Fsz,
                                 dec_ffn_b1 + (size_t)l*Fsz, ffn, Md, Fsz, Dsz, 1);
        gemm_tf32<<<gD_D, blk>>>(ffn, dec_ffn_w2 + (size_t)l*Fsz*Dsz,
                                 dec_ffn_b2 + (size_t)l*Dsz, dtmp, Md, Dsz, Fsz, 0);
        add_ln_kernel<<<Md, 128>>>(dd, dtmp, dec_ln_s + (size_t)(l*3+2)*Dsz,
                                             dec_ln_b + (size_t)(l*3+2)*Dsz);
    }

    out_proj_kernel<<<Md, 128>>>(dd, out_w, out_b, (float*)d_out);
}